// round 13
// baseline (speedup 1.0000x reference)
#include <cuda_runtime.h>
#include <cuda_fp16.h>
#include <cstdint>

#define NH     16
#define DMODEL 1024
#define HDIM   64
#define NEMB   40001
#define NB     2
#define SEQ    512

// ---------------- device scratch ----------------
__device__ float g_Tx[NEMB * NH];
__device__ float g_Ty[NEMB * NH];
__device__ __half g_bias[(size_t)NB * NH * SEQ * SEQ];   // fp16 bias (16.7MB)

// fp16 hi/lo split operands
__device__ __half g_actH[3 * DMODEL * DMODEL];   // q,k,v activations [m][k]
__device__ __half g_actL[3 * DMODEL * DMODEL];
__device__ __half g_WtH[4 * DMODEL * DMODEL];    // Wq,Wk,Wv,Wo transposed [n][k] (hi only)
// projected Q/K/V in [b][h][seq][d], fp16 hi/lo (Q pre-scaled by 0.125)
__device__ __half g_QH[NB * NH * SEQ * HDIM], g_QL[NB * NH * SEQ * HDIM];
__device__ __half g_KH[NB * NH * SEQ * HDIM], g_KL[NB * NH * SEQ * HDIM];
__device__ __half g_VH[NB * NH * SEQ * HDIM];
// attention output hi/lo, [b*q][h*64+d] row-major 1024x1024
__device__ __half g_attH[DMODEL * DMODEL];
__device__ __half g_attL[DMODEL * DMODEL];

// ---------------- non-gated PTX helpers ----------------
__device__ __forceinline__ uint32_t smem_u32(const void* p) {
    uint32_t a;
    asm("{ .reg .u64 t; cvta.to.shared.u64 t, %1; cvt.u32.u64 %0, t; }" : "=r"(a) : "l"(p));
    return a;
}
__device__ __forceinline__ void cp_async16(uint32_t saddr, const void* gptr) {
    asm volatile("cp.async.cg.shared.global [%0], [%1], 16;" :: "r"(saddr), "l"(gptr) : "memory");
}
#define CP_COMMIT() asm volatile("cp.async.commit_group;" ::: "memory")
#define CP_WAIT(n)  asm volatile("cp.async.wait_group %0;" :: "n"(n) : "memory")

__device__ __forceinline__ void ldsm_x4(uint32_t* r, uint32_t addr) {
    asm volatile("ldmatrix.sync.aligned.m8n8.x4.shared.b16 {%0,%1,%2,%3}, [%4];"
                 : "=r"(r[0]), "=r"(r[1]), "=r"(r[2]), "=r"(r[3]) : "r"(addr));
}
__device__ __forceinline__ void ldsm_x4_trans(uint32_t* r, uint32_t addr) {
    asm volatile("ldmatrix.sync.aligned.m8n8.x4.trans.shared.b16 {%0,%1,%2,%3}, [%4];"
                 : "=r"(r[0]), "=r"(r[1]), "=r"(r[2]), "=r"(r[3]) : "r"(addr));
}
__device__ __forceinline__ void mma16816(float* d, const uint32_t* a, const uint32_t* b) {
    asm volatile("mma.sync.aligned.m16n8k16.row.col.f32.f16.f16.f32 "
                 "{%0,%1,%2,%3}, {%4,%5,%6,%7}, {%8,%9}, {%0,%1,%2,%3};"
                 : "+f"(d[0]), "+f"(d[1]), "+f"(d[2]), "+f"(d[3])
                 : "r"(a[0]), "r"(a[1]), "r"(a[2]), "r"(a[3]), "r"(b[0]), "r"(b[1]));
}
// pack two floats into fp16x2 hi part + fp16x2 residual part
__device__ __forceinline__ void packhl(float a, float b, uint32_t& hh, uint32_t& ll) {
    __half2 h2 = __floats2half2_rn(a, b);
    float2 f = __half22float2(h2);
    __half2 l2 = __floats2half2_rn(a - f.x, b - f.y);
    hh = *reinterpret_cast<uint32_t*>(&h2);
    ll = *reinterpret_cast<uint32_t*>(&l2);
}

// ---------------- kernel 1: project embedding tables through Wb ----------------
__global__ __launch_bounds__(256) void k_project(const float* __restrict__ xt,
                                                 const float* __restrict__ yt,
                                                 const float* __restrict__ Wb) {
    int id = blockIdx.x * 256 + threadIdx.x;
    if (id >= 2 * NEMB * NH) return;
    int which = (id >= NEMB * NH);
    int rid = which ? id - NEMB * NH : id;
    int r = rid >> 4, h = rid & 15;
    const float4* row = (const float4*)((which ? yt : xt) + (size_t)r * 256 + h * 16);
    const float4* wb = (const float4*)Wb;
    float s = 0.f;
#pragma unroll
    for (int q = 0; q < 4; q++) {
        float4 v = row[q], w = wb[q];
        s += v.x * w.x + v.y * w.y + v.z * w.z + v.w * w.w;
    }
    (which ? g_Ty : g_Tx)[rid] = s;
}

// ---------------- kernel 2: positional bias (fp16 output) ----------------
__global__ __launch_bounds__(256) void k_bias(const float* __restrict__ qx,
                                              const float* __restrict__ qy,
                                              const float* __restrict__ kx,
                                              const float* __restrict__ ky,
                                              const float* __restrict__ bbp) {
    __shared__ float sm[16 * 256];
    int b = blockIdx.z;
    int i0 = blockIdx.y * 16, j0 = blockIdx.x * 16;
    int t = threadIdx.x;
    int i = i0 + (t >> 4), j = j0 + (t & 15);
    float bb = bbp[0];
    float dx = qx[b * SEQ + j] - kx[b * SEQ + i];
    float dy = qy[b * SEQ + j] - ky[b * SEQ + i];
    dx = fminf(fmaxf(dx, -1000.f), 1000.f);
    dy = fminf(fmaxf(dy, -1000.f), 1000.f);
    int ix = (int)rintf((dx + 1000.f) * 20.f);
    int iy = (int)rintf((dy + 1000.f) * 20.f);
    const float4* px = (const float4*)(g_Tx + (size_t)ix * 16);
    const float4* py = (const float4*)(g_Ty + (size_t)iy * 16);
#pragma unroll
    for (int q = 0; q < 4; q++) {
        float4 a = px[q], c = py[q];
        float v0 = a.x + c.x + bb, v1 = a.y + c.y + bb;
        float v2 = a.z + c.z + bb, v3 = a.w + c.w + bb;
        sm[(q * 4 + 0) * 256 + t] = 1.f / (1.f + __expf(-v0));
        sm[(q * 4 + 1) * 256 + t] = 1.f / (1.f + __expf(-v1));
        sm[(q * 4 + 2) * 256 + t] = 1.f / (1.f + __expf(-v2));
        sm[(q * 4 + 3) * 256 + t] = 1.f / (1.f + __expf(-v3));
    }
    __syncthreads();
    int h = t >> 4, w = t & 15;
#pragma unroll
    for (int ii = 0; ii < 16; ii++) {
        g_bias[(((size_t)(b * NH + h)) * SEQ + (i0 + ii)) * SEQ + (j0 + w)] =
            __float2half(sm[h * 256 + ii * 16 + w]);
    }
}

// ---------------- fp16 hi/lo split helpers ----------------
__device__ __forceinline__ void split4h(float4 x, __half2* ph, __half2* pl) {
    __half2 h01 = __floats2half2_rn(x.x, x.y);
    __half2 h23 = __floats2half2_rn(x.z, x.w);
    float2 f01 = __half22float2(h01), f23 = __half22float2(h23);
    ph[0] = h01; ph[1] = h23;
    pl[0] = __floats2half2_rn(x.x - f01.x, x.y - f01.y);
    pl[1] = __floats2half2_rn(x.z - f23.x, x.w - f23.y);
}

// ---------------- merged conversion kernel: activations + weights ----------------
__global__ __launch_bounds__(256) void k_conv(const float* __restrict__ q,
                                              const float* __restrict__ k,
                                              const float* __restrict__ v,
                                              const float* __restrict__ Wq,
                                              const float* __restrict__ Wk,
                                              const float* __restrict__ Wv,
                                              const float* __restrict__ Wo) {
    __shared__ float t[32][33];
    int bidx = blockIdx.x, tid = threadIdx.x;
    if (bidx < 3072) {
        int z = bidx >> 10;
        const float* src = (z == 0) ? q : (z == 1) ? k : v;
        __half* H = g_actH + (size_t)z * DMODEL * DMODEL;
        __half* L = g_actL + (size_t)z * DMODEL * DMODEL;
        int i = (bidx & 1023) * 256 + tid;
        float4 x = ((const float4*)src)[i];
        split4h(x, (__half2*)(H + (size_t)i * 4), (__half2*)(L + (size_t)i * 4));
    } else {
        int w = bidx - 3072;
        int z = w >> 10, rem = w & 1023;
        const float* W = (z == 0) ? Wq : (z == 1) ? Wk : (z == 2) ? Wv : Wo;
        __half* H = g_WtH + (size_t)z * DMODEL * DMODEL;
        int nb = (rem & 31) * 32, kb = (rem >> 5) * 32;
        int tx = tid & 31, ty = tid >> 5;   // 32 x 8
#pragma unroll
        for (int i = 0; i < 4; i++)
            t[ty + i * 8][tx] = W[(size_t)(kb + ty + i * 8) * DMODEL + nb + tx];
        __syncthreads();
#pragma unroll
        for (int i = 0; i < 4; i++) {
            int n = nb + ty + i * 8, kk = kb + tx;
            H[(size_t)n * DMODEL + kk] = __float2half(t[tx][ty + i * 8]);
        }
    }
}

// ---------------- warp-mma GEMM: C = (Ah[+Al]) @ Bh^T + bias ----------------
// Single K pass; per stage holds Ah, Al, B tiles; each B fragment consumed by both
// hi and (optionally) lo mma. useLo=false -> 1-term (V projection).
// BM=BN=64, BK=32, 128 threads, 4 warps (2m x 2n), 3-stage pipeline, 1 sync/iter.
#define NKITER 32
#define STAGES 3

template <int MODE>
__device__ __forceinline__ void mma_body(const __half* __restrict__ Ah,
                                         const __half* __restrict__ Al,
                                         const __half* __restrict__ Bh,
                                         const float* __restrict__ bias,
                                         __half* __restrict__ OH,
                                         __half* __restrict__ OL,
                                         float* __restrict__ OF,
                                         float scale, bool useLo) {
    __shared__ __align__(1024) char smem[STAGES][12288];   // Ah 4KB | Al 4KB | B 4KB
    int tid = threadIdx.x, lane = tid & 31, wid = tid >> 5;
    int wm = wid & 1, wn = wid >> 1;                  // 2 x 2 warp grid
    int m0 = blockIdx.y * 64, n0 = blockIdx.x * 64;
    uint32_t sbase = smem_u32(smem);

    float acc[2][4][4];
#pragma unroll
    for (int i = 0; i < 2; i++)
#pragma unroll
        for (int j = 0; j < 4; j++)
#pragma unroll
            for (int r = 0; r < 4; r++) acc[i][j][r] = 0.f;

    auto issue_tile = [&](int ki, int s) {
        int kk = ki * 32;
        uint32_t sAh = sbase + s * 12288, sAl = sAh + 4096, sB = sAh + 8192;
#pragma unroll
        for (int j = 0; j < 2; j++) {
            int idx = tid + j * 128;                   // 256 chunks per tile
            int row = idx >> 2, c = idx & 3;
            int cs = c ^ ((row >> 1) & 3);
            size_t ga = (size_t)(m0 + row) * DMODEL + kk + c * 8;
            cp_async16(sAh + row * 64 + cs * 16, Ah + ga);
            if (useLo) cp_async16(sAl + row * 64 + cs * 16, Al + ga);
            cp_async16(sB + row * 64 + cs * 16, Bh + (size_t)(n0 + row) * DMODEL + kk + c * 8);
        }
        CP_COMMIT();
    };

    issue_tile(0, 0);
    issue_tile(1, 1);
    for (int ki = 0; ki < NKITER; ki++) {
        int s = ki % STAGES;
        if (ki + 1 < NKITER) { CP_WAIT(1); } else { CP_WAIT(0); }
        __syncthreads();
        if (ki + 2 < NKITER) issue_tile(ki + 2, (ki + 2) % STAGES);
        uint32_t sAh = sbase + s * 12288, sAl = sAh + 4096, sB = sAh + 8192;
#pragma unroll
        for (int kq = 0; kq < 2; kq++) {
            uint32_t ah[2][4], al[2][4];
#pragma unroll
            for (int im = 0; im < 2; im++) {
                int row = wm * 32 + im * 16 + (lane & 15);
                int c = kq * 2 + (lane >> 4);
                int cs = c ^ ((row >> 1) & 3);
                ldsm_x4(ah[im], sAh + row * 64 + cs * 16);
                if (useLo) ldsm_x4(al[im], sAl + row * 64 + cs * 16);
            }
#pragma unroll
            for (int jnp = 0; jnp < 2; jnp++) {
                uint32_t bf[4];                          // 2 n-tiles x 2 k8 halves
                int mat = lane >> 3;
                int jn2 = jnp * 2 + (mat >> 1);
                int cc = kq * 2 + (mat & 1);
                int row = wn * 32 + jn2 * 8 + (lane & 7);
                int cs = cc ^ ((row >> 1) & 3);
                ldsm_x4(bf, sB + row * 64 + cs * 16);
#pragma unroll
                for (int im = 0; im < 2; im++) {
                    mma16816(acc[im][jnp * 2 + 0], ah[im], &bf[0]);
                    mma16816(acc[im][jnp * 2 + 1], ah[im], &bf[2]);
                    if (useLo) {
                        mma16816(acc[im][jnp * 2 + 0], al[im], &bf[0]);
                        mma16816(acc[im][jnp * 2 + 1], al[im], &bf[2]);
                    }
                }
            }
        }
    }

    // epilogue
#pragma unroll
    for (int im = 0; im < 2; im++) {
#pragma unroll
        for (int jn = 0; jn < 4; jn++) {
            int col = n0 + wn * 32 + jn * 8 + 2 * (lane & 3);
            float b0 = bias[col], b1 = bias[col + 1];
#pragma unroll
            for (int half = 0; half < 2; half++) {
                int m = m0 + wm * 32 + im * 16 + (lane >> 2) + half * 8;
                float v0 = (acc[im][jn][half * 2 + 0] + b0) * scale;
                float v1 = (acc[im][jn][half * 2 + 1] + b1) * scale;
                if (MODE == 0) {
                    int bidx = m >> 9, nseq = m & 511;
                    int h = col >> 6, d = col & 63;
                    size_t idx = (((size_t)(bidx * NH + h)) * SEQ + nseq) * HDIM + d;
                    uint32_t hh, ll;
                    packhl(v0, v1, hh, ll);
                    *(uint32_t*)(OH + idx) = hh;
                    if (OL) *(uint32_t*)(OL + idx) = ll;
                } else {
                    *(float2*)(OF + (size_t)m * DMODEL + col) = make_float2(v0, v1);
                }
            }
        }
    }
}

__global__ __launch_bounds__(128) void k_mma_qkv(const float* __restrict__ bq,
                                                 const float* __restrict__ bk,
                                                 const float* __restrict__ bv) {
    int z = blockIdx.z;
    const __half* Ah = g_actH + (size_t)z * DMODEL * DMODEL;
    const __half* Al = g_actL + (size_t)z * DMODEL * DMODEL;
    const __half* Bh = g_WtH + (size_t)z * DMODEL * DMODEL;
    const float* bias = (z == 0) ? bq : (z == 1) ? bk : bv;
    __half* OH = (z == 0) ? g_QH : (z == 1) ? g_KH : g_VH;
    __half* OL = (z == 0) ? g_QL : (z == 1) ? g_KL : nullptr;   // V needs hi only
    float scale = (z == 0) ? 0.125f : 1.0f;
    mma_body<0>(Ah, Al, Bh, bias, OH, OL, nullptr, scale, z != 2);  // V: 1-term
}

__global__ __launch_bounds__(128) void k_mma_out(const float* __restrict__ bo,
                                                 float* __restrict__ out) {
    mma_body<1>(g_attH, g_attL, g_WtH + (size_t)3 * DMODEL * DMODEL,
                bo, nullptr, nullptr, out, 1.0f, true);
}

// ---------------- tensor-core flash attention, 8 warps, fixed-max softmax ----------------
// ldsm_x4-batched K and V fragment loads (two n-tiles / two j-columns per instr).
__global__ __launch_bounds__(256) void k_attn() {
    __shared__ __align__(1024) char smbuf[40960];
    uint32_t sQH = smem_u32(smbuf), sQL = sQH + 8192;
    uint32_t sKH = sQH + 16384, sKL = sQH + 24576;
    uint32_t sVH = sQH + 32768;
    int b = blockIdx.z, h = blockIdx.y, q0 = blockIdx.x * 64;
    int tid = threadIdx.x, lane = tid & 31, wid = tid >> 5;
    int wq = wid & 3, g = wid >> 2;
    size_t hb = (size_t)(b * NH + h) * SEQ * HDIM;
    const __half *QHp = g_QH + hb, *QLp = g_QL + hb;
    const __half *KHp = g_KH + hb, *KLp = g_KL + hb;
    const __half *VHp = g_VH + hb;
    const __half* Bg = g_bias + ((size_t)(b * NH + h) * SEQ + q0) * SEQ;

#pragma unroll
    for (int u = 0; u < 2; u++) {
        int idx = u * 256 + tid;
        int row = idx >> 3, c = idx & 7, cs = c ^ (row & 7);
        size_t go = (size_t)(q0 + row) * HDIM + c * 8;
        cp_async16(sQH + row * 128 + cs * 16, QHp + go);
        cp_async16(sQL + row * 128 + cs * 16, QLp + go);
    }
    CP_COMMIT();
    CP_WAIT(0);
    __syncthreads();

    uint32_t qh[4][4], ql[4][4];
#pragma unroll
    for (int kk = 0; kk < 4; kk++) {
        int row = wq * 16 + (lane & 15);
        int c = kk * 2 + (lane >> 4), cs = c ^ (row & 7);
        ldsm_x4(qh[kk], sQH + row * 128 + cs * 16);
        ldsm_x4(ql[kk], sQL + row * 128 + cs * 16);
    }

    float o[8][4];
#pragma unroll
    for (int j = 0; j < 8; j++)
#pragma unroll
        for (int r = 0; r < 4; r++) o[j][r] = 0.f;
    float lA = 0.f, lB = 0.f;
    int br0 = wq * 16 + (lane >> 2);
    int bc = 2 * (lane & 3);
    int goff = g * 32;

    for (int k0 = 0; k0 < SEQ; k0 += 64) {
        __syncthreads();
#pragma unroll
        for (int u = 0; u < 2; u++) {
            int idx = u * 256 + tid;
            int row = idx >> 3, c = idx & 7, cs = c ^ (row & 7);
            size_t go = (size_t)(k0 + row) * HDIM + c * 8;
            cp_async16(sKH + row * 128 + cs * 16, KHp + go);
            cp_async16(sKL + row * 128 + cs * 16, KLp + go);
            cp_async16(sVH + row * 128 + cs * 16, VHp + go);
        }
        CP_COMMIT();
        float2 bias0[4], bias1[4];
#pragma unroll
        for (int jt = 0; jt < 4; jt++) {
            __half2 t0 = *(const __half2*)(Bg + (size_t)br0 * SEQ + k0 + goff + jt * 8 + bc);
            __half2 t1 = *(const __half2*)(Bg + (size_t)(br0 + 8) * SEQ + k0 + goff + jt * 8 + bc);
            bias0[jt] = __half22float2(t0);
            bias1[jt] = __half22float2(t1);
        }
        CP_WAIT(0);
        __syncthreads();

        // S tiles: batched K loads (two jt per ldsm_x4)
        float s[4][4];
#pragma unroll
        for (int jt = 0; jt < 4; jt++)
            s[jt][0] = s[jt][1] = s[jt][2] = s[jt][3] = 0.f;
#pragma unroll
        for (int kk = 0; kk < 4; kk++) {
#pragma unroll
            for (int p = 0; p < 2; p++) {
                uint32_t kh[4], kl[4];
                int mat = lane >> 3;
                int jt2 = p * 2 + (mat >> 1);
                int cc = kk * 2 + (mat & 1);
                int row = goff + jt2 * 8 + (lane & 7);
                int cs = cc ^ (row & 7);
                ldsm_x4(kh, sKH + row * 128 + cs * 16);
                ldsm_x4(kl, sKL + row * 128 + cs * 16);
                mma16816(s[p * 2 + 0], qh[kk], &kh[0]);
                mma16816(s[p * 2 + 0], ql[kk], &kh[0]);
                mma16816(s[p * 2 + 0], qh[kk], &kl[0]);
                mma16816(s[p * 2 + 1], qh[kk], &kh[2]);
                mma16816(s[p * 2 + 1], ql[kk], &kh[2]);
                mma16816(s[p * 2 + 1], qh[kk], &kl[2]);
            }
        }

#pragma unroll
        for (int jt = 0; jt < 4; jt++) {
            s[jt][0] = __expf(s[jt][0] + bias0[jt].x);
            s[jt][1] = __expf(s[jt][1] + bias0[jt].y);
            s[jt][2] = __expf(s[jt][2] + bias1[jt].x);
            s[jt][3] = __expf(s[jt][3] + bias1[jt].y);
            lA += s[jt][0] + s[jt][1];
            lB += s[jt][2] + s[jt][3];
        }

        uint32_t ph[2][4], pl[2][4];
#pragma unroll
        for (int kk = 0; kk < 2; kk++) {
            packhl(s[2 * kk][0], s[2 * kk][1], ph[kk][0], pl[kk][0]);
            packhl(s[2 * kk][2], s[2 * kk][3], ph[kk][1], pl[kk][1]);
            packhl(s[2 * kk + 1][0], s[2 * kk + 1][1], ph[kk][2], pl[kk][2]);
            packhl(s[2 * kk + 1][2], s[2 * kk + 1][3], ph[kk][3], pl[kk][3]);
        }

        // O += P @ V: batched V loads (two j per ldsm_x4_trans)
#pragma unroll
        for (int kk = 0; kk < 2; kk++) {
#pragma unroll
            for (int jp = 0; jp < 4; jp++) {
                uint32_t vh[4];
                int row = goff + kk * 16 + (lane & 15);
                int c = jp * 2 + (lane >> 4);
                int cs = c ^ (row & 7);
                ldsm_x4_trans(vh, sVH + row * 128 + cs * 16);
                mma16816(o[jp * 2 + 0], ph[kk], &vh[0]);
                mma16816(o[jp * 2 + 0], pl[kk], &vh[0]);
                mma16816(o[jp * 2 + 1], ph[kk], &vh[2]);
                mma16816(o[jp * 2 + 1], pl[kk], &vh[2]);
            }
        }
    }

    lA += __shfl_xor_sync(0xffffffffu, lA, 1);
    lA += __shfl_xor_sync(0xffffffffu, lA, 2);
    lB += __shfl_xor_sync(0xffffffffu, lB, 1);
    lB += __shfl_xor_sync(0xffffffffu, lB, 2);

    float* scr = (float*)(smbuf + 16384);
    float* sml = (float*)(smbuf + 32768);
    __syncthreads();
    if (g == 1) {
#pragma unroll
        for (int j = 0; j < 8; j++) {
            scr[br0 * 64 + j * 8 + bc] = o[j][0];
            scr[br0 * 64 + j * 8 + bc + 1] = o[j][1];
            scr[(br0 + 8) * 64 + j * 8 + bc] = o[j][2];
            scr[(br0 + 8) * 64 + j * 8 + bc + 1] = o[j][3];
        }
        if ((lane & 3) == 0) {
            sml[br0] = lA;
            sml[br0 + 8] = lB;
        }
    }
    __syncthreads();
    if (g == 0) {
        float r0 = 1.f / (lA + sml[br0]);
        float r1 = 1.f / (lB + sml[br0 + 8]);
        int rq0 = q0 + br0;
#pragma unroll
        for (int j = 0; j < 8; j++) {
            float v0 = (o[j][0] + scr[br0 * 64 + j * 8 + bc]) * r0;
            float v1 = (o[j][1] + scr[br0 * 64 + j * 8 + bc + 1]) * r0;
            float v2 = (o[j][2] + scr[(br0 + 8) * 64 + j * 8 + bc]) * r1;
            float v3 = (o[j][3] + scr[(br0 + 8) * 64 + j * 8 + bc + 1]) * r1;
            size_t i0 = ((size_t)(b * SEQ + rq0) * NH + h) * HDIM + j * 8 + bc;
            size_t i1 = ((size_t)(b * SEQ + rq0 + 8) * NH + h) * HDIM + j * 8 + bc;
            uint32_t hh, ll;
            packhl(v0, v1, hh, ll);
            *(uint32_t*)(g_attH + i0) = hh;
            *(uint32_t*)(g_attL + i0) = ll;
            packhl(v2, v3, hh, ll);
            *(uint32_t*)(g_attH + i1) = hh;
            *(uint32_t*)(g_attL + i1) = ll;
        }
    }
}

// ---------------- launch: two-stream fork/join for graph-level overlap ----------------
extern "C" void kernel_launch(void* const* d_in, const int* in_sizes, int n_in,
                              void* d_out, int out_size) {
    (void)in_sizes; (void)n_in; (void)out_size;
    const float* query = (const float*)d_in[0];
    const float* key   = (const float*)d_in[1];
    const float* value = (const float*)d_in[2];
    const float* qx    = (const float*)d_in[3];
    const float* qy    = (const float*)d_in[4];
    const float* kx    = (const float*)d_in[5];
    const float* ky    = (const float*)d_in[6];
    const float* Wq    = (const float*)d_in[7];
    const float* bq    = (const float*)d_in[8];
    const float* Wk    = (const float*)d_in[9];
    const float* bk    = (const float*)d_in[10];
    const float* Wv    = (const float*)d_in[11];
    const float* bv    = (const float*)d_in[12];
    const float* Wo    = (const float*)d_in[13];
    const float* bo    = (const float*)d_in[14];
    const float* xt    = (const float*)d_in[15];
    const float* yt    = (const float*)d_in[16];
    const float* Wb    = (const float*)d_in[17];
    const float* bb    = (const float*)d_in[18];
    float* out = (float*)d_out;

    static cudaStream_t s1 = nullptr;
    static cudaEvent_t eFork = nullptr, eJoin = nullptr;
    if (!s1) {
        cudaStreamCreateWithFlags(&s1, cudaStreamNonBlocking);
        cudaEventCreateWithFlags(&eFork, cudaEventDisableTiming);
        cudaEventCreateWithFlags(&eJoin, cudaEventDisableTiming);
    }

    // fork: side stream runs the memory-bound bias chain
    cudaEventRecord(eFork, 0);
    cudaStreamWaitEvent(s1, eFork, 0);
    k_project<<<(2 * NEMB * NH + 255) / 256, 256, 0, s1>>>(xt, yt, Wb);
    k_bias<<<dim3(SEQ / 16, SEQ / 16, NB), 256, 0, s1>>>(qx, qy, kx, ky, bb);
    cudaEventRecord(eJoin, s1);

    // main stream: mma-bound projection chain (overlaps with bias chain)
    k_conv<<<7168, 256>>>(query, key, value, Wq, Wk, Wv, Wo);
    k_mma_qkv<<<dim3(DMODEL / 64, (NB * SEQ) / 64, 3), 128>>>(bq, bk, bv);

    // join: attention needs both chains
    cudaStreamWaitEvent(0, eJoin, 0);
    k_attn<<<dim3(SEQ / 64, NH, NB), 256>>>();
    k_mma_out<<<dim3(DMODEL / 64, DMODEL / 64), 128>>>(bo, out);
}

// round 14
// speedup vs baseline: 1.0454x; 1.0454x over previous
#include <cuda_runtime.h>
#include <cuda_fp16.h>
#include <cstdint>

#define NH     16
#define DMODEL 1024
#define HDIM   64
#define NEMB   40001
#define NB     2
#define SEQ    512

// ---------------- device scratch ----------------
__device__ float g_Tx[NEMB * NH];
__device__ float g_Ty[NEMB * NH];
__device__ __half g_bias[(size_t)NB * NH * SEQ * SEQ];   // fp16 bias (16.7MB)

// fp16 hi/lo split operands
__device__ __half g_actH[3 * DMODEL * DMODEL];   // q,k,v activations [m][k]
__device__ __half g_actL[3 * DMODEL * DMODEL];
__device__ __half g_WtH[4 * DMODEL * DMODEL];    // Wq,Wk,Wv,Wo transposed [n][k] (hi only)
// projected Q/K/V in [b][h][seq][d], fp16 hi/lo (Q pre-scaled by 0.125)
__device__ __half g_QH[NB * NH * SEQ * HDIM], g_QL[NB * NH * SEQ * HDIM];
__device__ __half g_KH[NB * NH * SEQ * HDIM], g_KL[NB * NH * SEQ * HDIM];
__device__ __half g_VH[NB * NH * SEQ * HDIM];
// attention output hi/lo, [b*q][h*64+d] row-major 1024x1024
__device__ __half g_attH[DMODEL * DMODEL];
__device__ __half g_attL[DMODEL * DMODEL];

// ---------------- non-gated PTX helpers ----------------
__device__ __forceinline__ uint32_t smem_u32(const void* p) {
    uint32_t a;
    asm("{ .reg .u64 t; cvta.to.shared.u64 t, %1; cvt.u32.u64 %0, t; }" : "=r"(a) : "l"(p));
    return a;
}
__device__ __forceinline__ void cp_async16(uint32_t saddr, const void* gptr) {
    asm volatile("cp.async.cg.shared.global [%0], [%1], 16;" :: "r"(saddr), "l"(gptr) : "memory");
}
#define CP_COMMIT() asm volatile("cp.async.commit_group;" ::: "memory")
#define CP_WAIT(n)  asm volatile("cp.async.wait_group %0;" :: "n"(n) : "memory")

__device__ __forceinline__ void ldsm_x4(uint32_t* r, uint32_t addr) {
    asm volatile("ldmatrix.sync.aligned.m8n8.x4.shared.b16 {%0,%1,%2,%3}, [%4];"
                 : "=r"(r[0]), "=r"(r[1]), "=r"(r[2]), "=r"(r[3]) : "r"(addr));
}
__device__ __forceinline__ void ldsm_x2(uint32_t* r, uint32_t addr) {
    asm volatile("ldmatrix.sync.aligned.m8n8.x2.shared.b16 {%0,%1}, [%2];"
                 : "=r"(r[0]), "=r"(r[1]) : "r"(addr));
}
__device__ __forceinline__ void ldsm_x2_trans(uint32_t* r, uint32_t addr) {
    asm volatile("ldmatrix.sync.aligned.m8n8.x2.trans.shared.b16 {%0,%1}, [%2];"
                 : "=r"(r[0]), "=r"(r[1]) : "r"(addr));
}
__device__ __forceinline__ void mma16816(float* d, const uint32_t* a, const uint32_t* b) {
    asm volatile("mma.sync.aligned.m16n8k16.row.col.f32.f16.f16.f32 "
                 "{%0,%1,%2,%3}, {%4,%5,%6,%7}, {%8,%9}, {%0,%1,%2,%3};"
                 : "+f"(d[0]), "+f"(d[1]), "+f"(d[2]), "+f"(d[3])
                 : "r"(a[0]), "r"(a[1]), "r"(a[2]), "r"(a[3]), "r"(b[0]), "r"(b[1]));
}
// pack two floats into fp16x2 hi part + fp16x2 residual part
__device__ __forceinline__ void packhl(float a, float b, uint32_t& hh, uint32_t& ll) {
    __half2 h2 = __floats2half2_rn(a, b);
    float2 f = __half22float2(h2);
    __half2 l2 = __floats2half2_rn(a - f.x, b - f.y);
    hh = *reinterpret_cast<uint32_t*>(&h2);
    ll = *reinterpret_cast<uint32_t*>(&l2);
}

// ---------------- kernel 1: project embedding tables through Wb ----------------
__global__ __launch_bounds__(256) void k_project(const float* __restrict__ xt,
                                                 const float* __restrict__ yt,
                                                 const float* __restrict__ Wb) {
    int id = blockIdx.x * 256 + threadIdx.x;
    if (id >= 2 * NEMB * NH) return;
    int which = (id >= NEMB * NH);
    int rid = which ? id - NEMB * NH : id;
    int r = rid >> 4, h = rid & 15;
    const float4* row = (const float4*)((which ? yt : xt) + (size_t)r * 256 + h * 16);
    const float4* wb = (const float4*)Wb;
    float s = 0.f;
#pragma unroll
    for (int q = 0; q < 4; q++) {
        float4 v = row[q], w = wb[q];
        s += v.x * w.x + v.y * w.y + v.z * w.z + v.w * w.w;
    }
    (which ? g_Ty : g_Tx)[rid] = s;
}

// ---------------- kernel 2: positional bias (fp16 output) ----------------
__global__ __launch_bounds__(256) void k_bias(const float* __restrict__ qx,
                                              const float* __restrict__ qy,
                                              const float* __restrict__ kx,
                                              const float* __restrict__ ky,
                                              const float* __restrict__ bbp) {
    __shared__ float sm[16 * 256];
    int b = blockIdx.z;
    int i0 = blockIdx.y * 16, j0 = blockIdx.x * 16;
    int t = threadIdx.x;
    int i = i0 + (t >> 4), j = j0 + (t & 15);
    float bb = bbp[0];
    float dx = qx[b * SEQ + j] - kx[b * SEQ + i];
    float dy = qy[b * SEQ + j] - ky[b * SEQ + i];
    dx = fminf(fmaxf(dx, -1000.f), 1000.f);
    dy = fminf(fmaxf(dy, -1000.f), 1000.f);
    int ix = (int)rintf((dx + 1000.f) * 20.f);
    int iy = (int)rintf((dy + 1000.f) * 20.f);
    const float4* px = (const float4*)(g_Tx + (size_t)ix * 16);
    const float4* py = (const float4*)(g_Ty + (size_t)iy * 16);
#pragma unroll
    for (int q = 0; q < 4; q++) {
        float4 a = px[q], c = py[q];
        float v0 = a.x + c.x + bb, v1 = a.y + c.y + bb;
        float v2 = a.z + c.z + bb, v3 = a.w + c.w + bb;
        sm[(q * 4 + 0) * 256 + t] = 1.f / (1.f + __expf(-v0));
        sm[(q * 4 + 1) * 256 + t] = 1.f / (1.f + __expf(-v1));
        sm[(q * 4 + 2) * 256 + t] = 1.f / (1.f + __expf(-v2));
        sm[(q * 4 + 3) * 256 + t] = 1.f / (1.f + __expf(-v3));
    }
    __syncthreads();
    int h = t >> 4, w = t & 15;
#pragma unroll
    for (int ii = 0; ii < 16; ii++) {
        g_bias[(((size_t)(b * NH + h)) * SEQ + (i0 + ii)) * SEQ + (j0 + w)] =
            __float2half(sm[h * 256 + ii * 16 + w]);
    }
}

// ---------------- fp16 hi/lo split helpers ----------------
__device__ __forceinline__ void split4h(float4 x, __half2* ph, __half2* pl) {
    __half2 h01 = __floats2half2_rn(x.x, x.y);
    __half2 h23 = __floats2half2_rn(x.z, x.w);
    float2 f01 = __half22float2(h01), f23 = __half22float2(h23);
    ph[0] = h01; ph[1] = h23;
    pl[0] = __floats2half2_rn(x.x - f01.x, x.y - f01.y);
    pl[1] = __floats2half2_rn(x.z - f23.x, x.w - f23.y);
}

// ---------------- merged conversion kernel: activations + weights ----------------
__global__ __launch_bounds__(256) void k_conv(const float* __restrict__ q,
                                              const float* __restrict__ k,
                                              const float* __restrict__ v,
                                              const float* __restrict__ Wq,
                                              const float* __restrict__ Wk,
                                              const float* __restrict__ Wv,
                                              const float* __restrict__ Wo) {
    __shared__ float t[32][33];
    int bidx = blockIdx.x, tid = threadIdx.x;
    if (bidx < 3072) {
        int z = bidx >> 10;
        const float* src = (z == 0) ? q : (z == 1) ? k : v;
        __half* H = g_actH + (size_t)z * DMODEL * DMODEL;
        __half* L = g_actL + (size_t)z * DMODEL * DMODEL;
        int i = (bidx & 1023) * 256 + tid;
        float4 x = ((const float4*)src)[i];
        split4h(x, (__half2*)(H + (size_t)i * 4), (__half2*)(L + (size_t)i * 4));
    } else {
        int w = bidx - 3072;
        int z = w >> 10, rem = w & 1023;
        const float* W = (z == 0) ? Wq : (z == 1) ? Wk : (z == 2) ? Wv : Wo;
        __half* H = g_WtH + (size_t)z * DMODEL * DMODEL;
        int nb = (rem & 31) * 32, kb = (rem >> 5) * 32;
        int tx = tid & 31, ty = tid >> 5;   // 32 x 8
#pragma unroll
        for (int i = 0; i < 4; i++)
            t[ty + i * 8][tx] = W[(size_t)(kb + ty + i * 8) * DMODEL + nb + tx];
        __syncthreads();
#pragma unroll
        for (int i = 0; i < 4; i++) {
            int n = nb + ty + i * 8, kk = kb + tx;
            H[(size_t)n * DMODEL + kk] = __float2half(t[tx][ty + i * 8]);
        }
    }
}

// ---------------- warp-mma GEMM: C = (Ah[+Al]) @ Bh^T + bias ----------------
// Single K pass; per stage holds Ah, Al, B tiles; each B fragment consumed by both
// hi and (optionally) lo mma. useLo=false -> 1-term (V projection).
// BM=BN=64, BK=32, 128 threads, 4 warps (2m x 2n), 3-stage pipeline, 1 sync/iter.
#define NKITER 32
#define STAGES 3

template <int MODE>
__device__ __forceinline__ void mma_body(const __half* __restrict__ Ah,
                                         const __half* __restrict__ Al,
                                         const __half* __restrict__ Bh,
                                         const float* __restrict__ bias,
                                         __half* __restrict__ OH,
                                         __half* __restrict__ OL,
                                         float* __restrict__ OF,
                                         float scale, bool useLo) {
    __shared__ __align__(1024) char smem[STAGES][12288];   // Ah 4KB | Al 4KB | B 4KB
    int tid = threadIdx.x, lane = tid & 31, wid = tid >> 5;
    int wm = wid & 1, wn = wid >> 1;                  // 2 x 2 warp grid
    int m0 = blockIdx.y * 64, n0 = blockIdx.x * 64;
    uint32_t sbase = smem_u32(smem);

    float acc[2][4][4];
#pragma unroll
    for (int i = 0; i < 2; i++)
#pragma unroll
        for (int j = 0; j < 4; j++)
#pragma unroll
            for (int r = 0; r < 4; r++) acc[i][j][r] = 0.f;

    auto issue_tile = [&](int ki, int s) {
        int kk = ki * 32;
        uint32_t sAh = sbase + s * 12288, sAl = sAh + 4096, sB = sAh + 8192;
#pragma unroll
        for (int j = 0; j < 2; j++) {
            int idx = tid + j * 128;                   // 256 chunks per tile
            int row = idx >> 2, c = idx & 3;
            int cs = c ^ ((row >> 1) & 3);
            size_t ga = (size_t)(m0 + row) * DMODEL + kk + c * 8;
            cp_async16(sAh + row * 64 + cs * 16, Ah + ga);
            if (useLo) cp_async16(sAl + row * 64 + cs * 16, Al + ga);
            cp_async16(sB + row * 64 + cs * 16, Bh + (size_t)(n0 + row) * DMODEL + kk + c * 8);
        }
        CP_COMMIT();
    };

    issue_tile(0, 0);
    issue_tile(1, 1);
    for (int ki = 0; ki < NKITER; ki++) {
        int s = ki % STAGES;
        if (ki + 1 < NKITER) { CP_WAIT(1); } else { CP_WAIT(0); }
        __syncthreads();
        if (ki + 2 < NKITER) issue_tile(ki + 2, (ki + 2) % STAGES);
        uint32_t sAh = sbase + s * 12288, sAl = sAh + 4096, sB = sAh + 8192;
#pragma unroll
        for (int kq = 0; kq < 2; kq++) {
            uint32_t ah[2][4], al[2][4];
#pragma unroll
            for (int im = 0; im < 2; im++) {
                int row = wm * 32 + im * 16 + (lane & 15);
                int c = kq * 2 + (lane >> 4);
                int cs = c ^ ((row >> 1) & 3);
                ldsm_x4(ah[im], sAh + row * 64 + cs * 16);
                if (useLo) ldsm_x4(al[im], sAl + row * 64 + cs * 16);
            }
#pragma unroll
            for (int jnp = 0; jnp < 2; jnp++) {
                uint32_t bf[4];                          // 2 n-tiles x 2 k8 halves
                int mat = lane >> 3;
                int jn2 = jnp * 2 + (mat >> 1);
                int cc = kq * 2 + (mat & 1);
                int row = wn * 32 + jn2 * 8 + (lane & 7);
                int cs = cc ^ ((row >> 1) & 3);
                ldsm_x4(bf, sB + row * 64 + cs * 16);
#pragma unroll
                for (int im = 0; im < 2; im++) {
                    mma16816(acc[im][jnp * 2 + 0], ah[im], &bf[0]);
                    mma16816(acc[im][jnp * 2 + 1], ah[im], &bf[2]);
                    if (useLo) {
                        mma16816(acc[im][jnp * 2 + 0], al[im], &bf[0]);
                        mma16816(acc[im][jnp * 2 + 1], al[im], &bf[2]);
                    }
                }
            }
        }
    }

    // epilogue
#pragma unroll
    for (int im = 0; im < 2; im++) {
#pragma unroll
        for (int jn = 0; jn < 4; jn++) {
            int col = n0 + wn * 32 + jn * 8 + 2 * (lane & 3);
            float b0 = bias[col], b1 = bias[col + 1];
#pragma unroll
            for (int half = 0; half < 2; half++) {
                int m = m0 + wm * 32 + im * 16 + (lane >> 2) + half * 8;
                float v0 = (acc[im][jn][half * 2 + 0] + b0) * scale;
                float v1 = (acc[im][jn][half * 2 + 1] + b1) * scale;
                if (MODE == 0) {
                    int bidx = m >> 9, nseq = m & 511;
                    int h = col >> 6, d = col & 63;
                    size_t idx = (((size_t)(bidx * NH + h)) * SEQ + nseq) * HDIM + d;
                    uint32_t hh, ll;
                    packhl(v0, v1, hh, ll);
                    *(uint32_t*)(OH + idx) = hh;
                    if (OL) *(uint32_t*)(OL + idx) = ll;
                } else {
                    *(float2*)(OF + (size_t)m * DMODEL + col) = make_float2(v0, v1);
                }
            }
        }
    }
}

__global__ __launch_bounds__(128) void k_mma_qkv(const float* __restrict__ bq,
                                                 const float* __restrict__ bk,
                                                 const float* __restrict__ bv) {
    int z = blockIdx.z;
    const __half* Ah = g_actH + (size_t)z * DMODEL * DMODEL;
    const __half* Al = g_actL + (size_t)z * DMODEL * DMODEL;
    const __half* Bh = g_WtH + (size_t)z * DMODEL * DMODEL;
    const float* bias = (z == 0) ? bq : (z == 1) ? bk : bv;
    __half* OH = (z == 0) ? g_QH : (z == 1) ? g_KH : g_VH;
    __half* OL = (z == 0) ? g_QL : (z == 1) ? g_KL : nullptr;   // V needs hi only
    float scale = (z == 0) ? 0.125f : 1.0f;
    mma_body<0>(Ah, Al, Bh, bias, OH, OL, nullptr, scale, z != 2);  // V: 1-term
}

__global__ __launch_bounds__(128) void k_mma_out(const float* __restrict__ bo,
                                                 float* __restrict__ out) {
    mma_body<1>(g_attH, g_attL, g_WtH + (size_t)3 * DMODEL * DMODEL,
                bo, nullptr, nullptr, out, 1.0f, true);
}

// ---------------- tensor-core flash attention, 8 warps, fixed-max softmax ----------------
// (R12 fragment-load pattern: ldsm_x2 per K n-tile, ldsm_x2_trans per V j-column.)
__global__ __launch_bounds__(256) void k_attn() {
    __shared__ __align__(1024) char smbuf[40960];
    uint32_t sQH = smem_u32(smbuf), sQL = sQH + 8192;
    uint32_t sKH = sQH + 16384, sKL = sQH + 24576;
    uint32_t sVH = sQH + 32768;
    int b = blockIdx.z, h = blockIdx.y, q0 = blockIdx.x * 64;
    int tid = threadIdx.x, lane = tid & 31, wid = tid >> 5;
    int wq = wid & 3, g = wid >> 2;
    size_t hb = (size_t)(b * NH + h) * SEQ * HDIM;
    const __half *QHp = g_QH + hb, *QLp = g_QL + hb;
    const __half *KHp = g_KH + hb, *KLp = g_KL + hb;
    const __half *VHp = g_VH + hb;
    const __half* Bg = g_bias + ((size_t)(b * NH + h) * SEQ + q0) * SEQ;

#pragma unroll
    for (int u = 0; u < 2; u++) {
        int idx = u * 256 + tid;
        int row = idx >> 3, c = idx & 7, cs = c ^ (row & 7);
        size_t go = (size_t)(q0 + row) * HDIM + c * 8;
        cp_async16(sQH + row * 128 + cs * 16, QHp + go);
        cp_async16(sQL + row * 128 + cs * 16, QLp + go);
    }
    CP_COMMIT();
    CP_WAIT(0);
    __syncthreads();

    uint32_t qh[4][4], ql[4][4];
#pragma unroll
    for (int kk = 0; kk < 4; kk++) {
        int row = wq * 16 + (lane & 15);
        int c = kk * 2 + (lane >> 4), cs = c ^ (row & 7);
        ldsm_x4(qh[kk], sQH + row * 128 + cs * 16);
        ldsm_x4(ql[kk], sQL + row * 128 + cs * 16);
    }

    float o[8][4];
#pragma unroll
    for (int j = 0; j < 8; j++)
#pragma unroll
        for (int r = 0; r < 4; r++) o[j][r] = 0.f;
    float lA = 0.f, lB = 0.f;
    int br0 = wq * 16 + (lane >> 2);
    int bc = 2 * (lane & 3);
    int goff = g * 32;

    for (int k0 = 0; k0 < SEQ; k0 += 64) {
        __syncthreads();
#pragma unroll
        for (int u = 0; u < 2; u++) {
            int idx = u * 256 + tid;
            int row = idx >> 3, c = idx & 7, cs = c ^ (row & 7);
            size_t go = (size_t)(k0 + row) * HDIM + c * 8;
            cp_async16(sKH + row * 128 + cs * 16, KHp + go);
            cp_async16(sKL + row * 128 + cs * 16, KLp + go);
            cp_async16(sVH + row * 128 + cs * 16, VHp + go);
        }
        CP_COMMIT();
        float2 bias0[4], bias1[4];
#pragma unroll
        for (int jt = 0; jt < 4; jt++) {
            __half2 t0 = *(const __half2*)(Bg + (size_t)br0 * SEQ + k0 + goff + jt * 8 + bc);
            __half2 t1 = *(const __half2*)(Bg + (size_t)(br0 + 8) * SEQ + k0 + goff + jt * 8 + bc);
            bias0[jt] = __half22float2(t0);
            bias1[jt] = __half22float2(t1);
        }
        CP_WAIT(0);
        __syncthreads();

        float s[4][4];
#pragma unroll
        for (int jt = 0; jt < 4; jt++) {
            s[jt][0] = s[jt][1] = s[jt][2] = s[jt][3] = 0.f;
#pragma unroll
            for (int kk = 0; kk < 4; kk++) {
                uint32_t kh[2], kl[2];
                int row = goff + jt * 8 + (lane & 7);
                int c = kk * 2 + ((lane >> 3) & 1), cs = c ^ (row & 7);
                ldsm_x2(kh, sKH + row * 128 + cs * 16);
                ldsm_x2(kl, sKL + row * 128 + cs * 16);
                mma16816(s[jt], qh[kk], kh);
                mma16816(s[jt], ql[kk], kh);
                mma16816(s[jt], qh[kk], kl);
            }
        }

#pragma unroll
        for (int jt = 0; jt < 4; jt++) {
            s[jt][0] = __expf(s[jt][0] + bias0[jt].x);
            s[jt][1] = __expf(s[jt][1] + bias0[jt].y);
            s[jt][2] = __expf(s[jt][2] + bias1[jt].x);
            s[jt][3] = __expf(s[jt][3] + bias1[jt].y);
            lA += s[jt][0] + s[jt][1];
            lB += s[jt][2] + s[jt][3];
        }

        uint32_t ph[2][4], pl[2][4];
#pragma unroll
        for (int kk = 0; kk < 2; kk++) {
            packhl(s[2 * kk][0], s[2 * kk][1], ph[kk][0], pl[kk][0]);
            packhl(s[2 * kk][2], s[2 * kk][3], ph[kk][1], pl[kk][1]);
            packhl(s[2 * kk + 1][0], s[2 * kk + 1][1], ph[kk][2], pl[kk][2]);
            packhl(s[2 * kk + 1][2], s[2 * kk + 1][3], ph[kk][3], pl[kk][3]);
        }

#pragma unroll
        for (int kk = 0; kk < 2; kk++) {
#pragma unroll
            for (int j = 0; j < 8; j++) {
                uint32_t vh[2];
                int row = goff + kk * 16 + (lane & 15);
                int cs = j ^ (row & 7);
                ldsm_x2_trans(vh, sVH + row * 128 + cs * 16);
                mma16816(o[j], ph[kk], vh);
                mma16816(o[j], pl[kk], vh);
            }
        }
    }

    lA += __shfl_xor_sync(0xffffffffu, lA, 1);
    lA += __shfl_xor_sync(0xffffffffu, lA, 2);
    lB += __shfl_xor_sync(0xffffffffu, lB, 1);
    lB += __shfl_xor_sync(0xffffffffu, lB, 2);

    float* scr = (float*)(smbuf + 16384);
    float* sml = (float*)(smbuf + 32768);
    __syncthreads();
    if (g == 1) {
#pragma unroll
        for (int j = 0; j < 8; j++) {
            scr[br0 * 64 + j * 8 + bc] = o[j][0];
            scr[br0 * 64 + j * 8 + bc + 1] = o[j][1];
            scr[(br0 + 8) * 64 + j * 8 + bc] = o[j][2];
            scr[(br0 + 8) * 64 + j * 8 + bc + 1] = o[j][3];
        }
        if ((lane & 3) == 0) {
            sml[br0] = lA;
            sml[br0 + 8] = lB;
        }
    }
    __syncthreads();
    if (g == 0) {
        float r0 = 1.f / (lA + sml[br0]);
        float r1 = 1.f / (lB + sml[br0 + 8]);
        int rq0 = q0 + br0;
#pragma unroll
        for (int j = 0; j < 8; j++) {
            float v0 = (o[j][0] + scr[br0 * 64 + j * 8 + bc]) * r0;
            float v1 = (o[j][1] + scr[br0 * 64 + j * 8 + bc + 1]) * r0;
            float v2 = (o[j][2] + scr[(br0 + 8) * 64 + j * 8 + bc]) * r1;
            float v3 = (o[j][3] + scr[(br0 + 8) * 64 + j * 8 + bc + 1]) * r1;
            size_t i0 = ((size_t)(b * SEQ + rq0) * NH + h) * HDIM + j * 8 + bc;
            size_t i1 = ((size_t)(b * SEQ + rq0 + 8) * NH + h) * HDIM + j * 8 + bc;
            uint32_t hh, ll;
            packhl(v0, v1, hh, ll);
            *(uint32_t*)(g_attH + i0) = hh;
            *(uint32_t*)(g_attL + i0) = ll;
            packhl(v2, v3, hh, ll);
            *(uint32_t*)(g_attH + i1) = hh;
            *(uint32_t*)(g_attL + i1) = ll;
        }
    }
}

// ---------------- launch: two-stream fork/join for graph-level overlap ----------------
extern "C" void kernel_launch(void* const* d_in, const int* in_sizes, int n_in,
                              void* d_out, int out_size) {
    (void)in_sizes; (void)n_in; (void)out_size;
    const float* query = (const float*)d_in[0];
    const float* key   = (const float*)d_in[1];
    const float* value = (const float*)d_in[2];
    const float* qx    = (const float*)d_in[3];
    const float* qy    = (const float*)d_in[4];
    const float* kx    = (const float*)d_in[5];
    const float* ky    = (const float*)d_in[6];
    const float* Wq    = (const float*)d_in[7];
    const float* bq    = (const float*)d_in[8];
    const float* Wk    = (const float*)d_in[9];
    const float* bk    = (const float*)d_in[10];
    const float* Wv    = (const float*)d_in[11];
    const float* bv    = (const float*)d_in[12];
    const float* Wo    = (const float*)d_in[13];
    const float* bo    = (const float*)d_in[14];
    const float* xt    = (const float*)d_in[15];
    const float* yt    = (const float*)d_in[16];
    const float* Wb    = (const float*)d_in[17];
    const float* bb    = (const float*)d_in[18];
    float* out = (float*)d_out;

    static cudaStream_t s1 = nullptr;
    static cudaEvent_t eFork = nullptr, eJoin = nullptr;
    if (!s1) {
        cudaStreamCreateWithFlags(&s1, cudaStreamNonBlocking);
        cudaEventCreateWithFlags(&eFork, cudaEventDisableTiming);
        cudaEventCreateWithFlags(&eJoin, cudaEventDisableTiming);
    }

    // fork: side stream runs the memory-bound bias chain
    cudaEventRecord(eFork, 0);
    cudaStreamWaitEvent(s1, eFork, 0);
    k_project<<<(2 * NEMB * NH + 255) / 256, 256, 0, s1>>>(xt, yt, Wb);
    k_bias<<<dim3(SEQ / 16, SEQ / 16, NB), 256, 0, s1>>>(qx, qy, kx, ky, bb);
    cudaEventRecord(eJoin, s1);

    // main stream: mma-bound projection chain (overlaps with bias chain)
    k_conv<<<7168, 256>>>(query, key, value, Wq, Wk, Wv, Wo);
    k_mma_qkv<<<dim3(DMODEL / 64, (NB * SEQ) / 64, 3), 128>>>(bq, bk, bv);

    // join: attention needs both chains
    cudaStreamWaitEvent(0, eJoin, 0);
    k_attn<<<dim3(SEQ / 64, NH, NB), 256>>>();
    k_mma_out<<<dim3(DMODEL / 64, DMODEL / 64), 128>>>(bo, out);
}

// round 15
// speedup vs baseline: 1.1091x; 1.0609x over previous
#include <cuda_runtime.h>
#include <cuda_fp16.h>
#include <cstdint>

#define NH     16
#define DMODEL 1024
#define HDIM   64
#define NEMB   40001
#define NB     2
#define SEQ    512

// ---------------- device scratch ----------------
__device__ float g_Tx[NEMB * NH];
__device__ float g_Ty[NEMB * NH];
__device__ __half g_bias[(size_t)NB * NH * SEQ * SEQ];   // fp16 bias (16.7MB)

// fp16 hi/lo split operands
__device__ __half g_actH[3 * DMODEL * DMODEL];   // q,k,v activations [m][k]
__device__ __half g_actL[3 * DMODEL * DMODEL];
__device__ __half g_WtH[4 * DMODEL * DMODEL];    // Wq,Wk,Wv,Wo transposed [n][k] (hi only)
// projected Q/K/V in [b][h][seq][d], fp16 hi/lo (Q pre-scaled by 0.125)
__device__ __half g_QH[NB * NH * SEQ * HDIM], g_QL[NB * NH * SEQ * HDIM];
__device__ __half g_KH[NB * NH * SEQ * HDIM], g_KL[NB * NH * SEQ * HDIM];
__device__ __half g_VH[NB * NH * SEQ * HDIM];
// attention output (hi only), [b*q][h*64+d] row-major 1024x1024
__device__ __half g_attH[DMODEL * DMODEL];

// ---------------- non-gated PTX helpers ----------------
__device__ __forceinline__ uint32_t smem_u32(const void* p) {
    uint32_t a;
    asm("{ .reg .u64 t; cvta.to.shared.u64 t, %1; cvt.u32.u64 %0, t; }" : "=r"(a) : "l"(p));
    return a;
}
__device__ __forceinline__ void cp_async16(uint32_t saddr, const void* gptr) {
    asm volatile("cp.async.cg.shared.global [%0], [%1], 16;" :: "r"(saddr), "l"(gptr) : "memory");
}
#define CP_COMMIT() asm volatile("cp.async.commit_group;" ::: "memory")
#define CP_WAIT(n)  asm volatile("cp.async.wait_group %0;" :: "n"(n) : "memory")

__device__ __forceinline__ void ldsm_x4(uint32_t* r, uint32_t addr) {
    asm volatile("ldmatrix.sync.aligned.m8n8.x4.shared.b16 {%0,%1,%2,%3}, [%4];"
                 : "=r"(r[0]), "=r"(r[1]), "=r"(r[2]), "=r"(r[3]) : "r"(addr));
}
__device__ __forceinline__ void ldsm_x2_trans(uint32_t* r, uint32_t addr) {
    asm volatile("ldmatrix.sync.aligned.m8n8.x2.trans.shared.b16 {%0,%1}, [%2];"
                 : "=r"(r[0]), "=r"(r[1]) : "r"(addr));
}
__device__ __forceinline__ void mma16816(float* d, const uint32_t* a, const uint32_t* b) {
    asm volatile("mma.sync.aligned.m16n8k16.row.col.f32.f16.f16.f32 "
                 "{%0,%1,%2,%3}, {%4,%5,%6,%7}, {%8,%9}, {%0,%1,%2,%3};"
                 : "+f"(d[0]), "+f"(d[1]), "+f"(d[2]), "+f"(d[3])
                 : "r"(a[0]), "r"(a[1]), "r"(a[2]), "r"(a[3]), "r"(b[0]), "r"(b[1]));
}
// pack two floats into fp16x2 hi part + fp16x2 residual part
__device__ __forceinline__ void packhl(float a, float b, uint32_t& hh, uint32_t& ll) {
    __half2 h2 = __floats2half2_rn(a, b);
    float2 f = __half22float2(h2);
    __half2 l2 = __floats2half2_rn(a - f.x, b - f.y);
    hh = *reinterpret_cast<uint32_t*>(&h2);
    ll = *reinterpret_cast<uint32_t*>(&l2);
}

// ---------------- kernel 1: project embedding tables through Wb ----------------
__global__ __launch_bounds__(256) void k_project(const float* __restrict__ xt,
                                                 const float* __restrict__ yt,
                                                 const float* __restrict__ Wb) {
    int id = blockIdx.x * 256 + threadIdx.x;
    if (id >= 2 * NEMB * NH) return;
    int which = (id >= NEMB * NH);
    int rid = which ? id - NEMB * NH : id;
    int r = rid >> 4, h = rid & 15;
    const float4* row = (const float4*)((which ? yt : xt) + (size_t)r * 256 + h * 16);
    const float4* wb = (const float4*)Wb;
    float s = 0.f;
#pragma unroll
    for (int q = 0; q < 4; q++) {
        float4 v = row[q], w = wb[q];
        s += v.x * w.x + v.y * w.y + v.z * w.z + v.w * w.w;
    }
    (which ? g_Ty : g_Tx)[rid] = s;
}

// ---------------- kernel 2: positional bias (fp16 output) ----------------
__global__ __launch_bounds__(256) void k_bias(const float* __restrict__ qx,
                                              const float* __restrict__ qy,
                                              const float* __restrict__ kx,
                                              const float* __restrict__ ky,
                                              const float* __restrict__ bbp) {
    __shared__ float sm[16 * 256];
    int b = blockIdx.z;
    int i0 = blockIdx.y * 16, j0 = blockIdx.x * 16;
    int t = threadIdx.x;
    int i = i0 + (t >> 4), j = j0 + (t & 15);
    float bb = bbp[0];
    float dx = qx[b * SEQ + j] - kx[b * SEQ + i];
    float dy = qy[b * SEQ + j] - ky[b * SEQ + i];
    dx = fminf(fmaxf(dx, -1000.f), 1000.f);
    dy = fminf(fmaxf(dy, -1000.f), 1000.f);
    int ix = (int)rintf((dx + 1000.f) * 20.f);
    int iy = (int)rintf((dy + 1000.f) * 20.f);
    const float4* px = (const float4*)(g_Tx + (size_t)ix * 16);
    const float4* py = (const float4*)(g_Ty + (size_t)iy * 16);
#pragma unroll
    for (int q = 0; q < 4; q++) {
        float4 a = px[q], c = py[q];
        float v0 = a.x + c.x + bb, v1 = a.y + c.y + bb;
        float v2 = a.z + c.z + bb, v3 = a.w + c.w + bb;
        sm[(q * 4 + 0) * 256 + t] = 1.f / (1.f + __expf(-v0));
        sm[(q * 4 + 1) * 256 + t] = 1.f / (1.f + __expf(-v1));
        sm[(q * 4 + 2) * 256 + t] = 1.f / (1.f + __expf(-v2));
        sm[(q * 4 + 3) * 256 + t] = 1.f / (1.f + __expf(-v3));
    }
    __syncthreads();
    int h = t >> 4, w = t & 15;
#pragma unroll
    for (int ii = 0; ii < 16; ii++) {
        g_bias[(((size_t)(b * NH + h)) * SEQ + (i0 + ii)) * SEQ + (j0 + w)] =
            __float2half(sm[h * 256 + ii * 16 + w]);
    }
}

// ---------------- fp16 hi/lo split helpers ----------------
__device__ __forceinline__ void split4h(float4 x, __half2* ph, __half2* pl) {
    __half2 h01 = __floats2half2_rn(x.x, x.y);
    __half2 h23 = __floats2half2_rn(x.z, x.w);
    float2 f01 = __half22float2(h01), f23 = __half22float2(h23);
    ph[0] = h01; ph[1] = h23;
    pl[0] = __floats2half2_rn(x.x - f01.x, x.y - f01.y);
    pl[1] = __floats2half2_rn(x.z - f23.x, x.w - f23.y);
}

// ---------------- merged conversion kernel: activations + weights ----------------
__global__ __launch_bounds__(256) void k_conv(const float* __restrict__ q,
                                              const float* __restrict__ k,
                                              const float* __restrict__ v,
                                              const float* __restrict__ Wq,
                                              const float* __restrict__ Wk,
                                              const float* __restrict__ Wv,
                                              const float* __restrict__ Wo) {
    __shared__ float t[32][33];
    int bidx = blockIdx.x, tid = threadIdx.x;
    if (bidx < 3072) {
        int z = bidx >> 10;
        const float* src = (z == 0) ? q : (z == 1) ? k : v;
        __half* H = g_actH + (size_t)z * DMODEL * DMODEL;
        __half* L = g_actL + (size_t)z * DMODEL * DMODEL;
        int i = (bidx & 1023) * 256 + tid;
        float4 x = ((const float4*)src)[i];
        split4h(x, (__half2*)(H + (size_t)i * 4), (__half2*)(L + (size_t)i * 4));
    } else {
        int w = bidx - 3072;
        int z = w >> 10, rem = w & 1023;
        const float* W = (z == 0) ? Wq : (z == 1) ? Wk : (z == 2) ? Wv : Wo;
        __half* H = g_WtH + (size_t)z * DMODEL * DMODEL;
        int nb = (rem & 31) * 32, kb = (rem >> 5) * 32;
        int tx = tid & 31, ty = tid >> 5;   // 32 x 8
#pragma unroll
        for (int i = 0; i < 4; i++)
            t[ty + i * 8][tx] = W[(size_t)(kb + ty + i * 8) * DMODEL + nb + tx];
        __syncthreads();
#pragma unroll
        for (int i = 0; i < 4; i++) {
            int n = nb + ty + i * 8, kk = kb + tx;
            H[(size_t)n * DMODEL + kk] = __float2half(t[tx][ty + i * 8]);
        }
    }
}

// ---------------- warp-mma GEMM: C = (Ah[+Al]) @ Bh^T + bias ----------------
// Single K pass; per stage holds Ah, Al, B tiles; each B fragment consumed by both
// hi and (optionally) lo mma. useLo=false -> 1-term.
// BM=BN=64, BK=32, 128 threads, 4 warps (2m x 2n), 3-stage pipeline, 1 sync/iter.
#define NKITER 32
#define STAGES 3

template <int MODE>
__device__ __forceinline__ void mma_body(const __half* __restrict__ Ah,
                                         const __half* __restrict__ Al,
                                         const __half* __restrict__ Bh,
                                         const float* __restrict__ bias,
                                         __half* __restrict__ OH,
                                         __half* __restrict__ OL,
                                         float* __restrict__ OF,
                                         float scale, bool useLo) {
    __shared__ __align__(1024) char smem[STAGES][12288];   // Ah 4KB | Al 4KB | B 4KB
    int tid = threadIdx.x, lane = tid & 31, wid = tid >> 5;
    int wm = wid & 1, wn = wid >> 1;                  // 2 x 2 warp grid
    int m0 = blockIdx.y * 64, n0 = blockIdx.x * 64;
    uint32_t sbase = smem_u32(smem);

    float acc[2][4][4];
#pragma unroll
    for (int i = 0; i < 2; i++)
#pragma unroll
        for (int j = 0; j < 4; j++)
#pragma unroll
            for (int r = 0; r < 4; r++) acc[i][j][r] = 0.f;

    auto issue_tile = [&](int ki, int s) {
        int kk = ki * 32;
        uint32_t sAh = sbase + s * 12288, sAl = sAh + 4096, sB = sAh + 8192;
#pragma unroll
        for (int j = 0; j < 2; j++) {
            int idx = tid + j * 128;                   // 256 chunks per tile
            int row = idx >> 2, c = idx & 3;
            int cs = c ^ ((row >> 1) & 3);
            size_t ga = (size_t)(m0 + row) * DMODEL + kk + c * 8;
            cp_async16(sAh + row * 64 + cs * 16, Ah + ga);
            if (useLo) cp_async16(sAl + row * 64 + cs * 16, Al + ga);
            cp_async16(sB + row * 64 + cs * 16, Bh + (size_t)(n0 + row) * DMODEL + kk + c * 8);
        }
        CP_COMMIT();
    };

    issue_tile(0, 0);
    issue_tile(1, 1);
    for (int ki = 0; ki < NKITER; ki++) {
        int s = ki % STAGES;
        if (ki + 1 < NKITER) { CP_WAIT(1); } else { CP_WAIT(0); }
        __syncthreads();
        if (ki + 2 < NKITER) issue_tile(ki + 2, (ki + 2) % STAGES);
        uint32_t sAh = sbase + s * 12288, sAl = sAh + 4096, sB = sAh + 8192;
#pragma unroll
        for (int kq = 0; kq < 2; kq++) {
            uint32_t ah[2][4], al[2][4];
#pragma unroll
            for (int im = 0; im < 2; im++) {
                int row = wm * 32 + im * 16 + (lane & 15);
                int c = kq * 2 + (lane >> 4);
                int cs = c ^ ((row >> 1) & 3);
                ldsm_x4(ah[im], sAh + row * 64 + cs * 16);
                if (useLo) ldsm_x4(al[im], sAl + row * 64 + cs * 16);
            }
#pragma unroll
            for (int jnp = 0; jnp < 2; jnp++) {
                uint32_t bf[4];                          // 2 n-tiles x 2 k8 halves
                int mat = lane >> 3;
                int jn2 = jnp * 2 + (mat >> 1);
                int cc = kq * 2 + (mat & 1);
                int row = wn * 32 + jn2 * 8 + (lane & 7);
                int cs = cc ^ ((row >> 1) & 3);
                ldsm_x4(bf, sB + row * 64 + cs * 16);
#pragma unroll
                for (int im = 0; im < 2; im++) {
                    mma16816(acc[im][jnp * 2 + 0], ah[im], &bf[0]);
                    mma16816(acc[im][jnp * 2 + 1], ah[im], &bf[2]);
                    if (useLo) {
                        mma16816(acc[im][jnp * 2 + 0], al[im], &bf[0]);
                        mma16816(acc[im][jnp * 2 + 1], al[im], &bf[2]);
                    }
                }
            }
        }
    }

    // epilogue
#pragma unroll
    for (int im = 0; im < 2; im++) {
#pragma unroll
        for (int jn = 0; jn < 4; jn++) {
            int col = n0 + wn * 32 + jn * 8 + 2 * (lane & 3);
            float b0 = bias[col], b1 = bias[col + 1];
#pragma unroll
            for (int half = 0; half < 2; half++) {
                int m = m0 + wm * 32 + im * 16 + (lane >> 2) + half * 8;
                float v0 = (acc[im][jn][half * 2 + 0] + b0) * scale;
                float v1 = (acc[im][jn][half * 2 + 1] + b1) * scale;
                if (MODE == 0) {
                    int bidx = m >> 9, nseq = m & 511;
                    int h = col >> 6, d = col & 63;
                    size_t idx = (((size_t)(bidx * NH + h)) * SEQ + nseq) * HDIM + d;
                    uint32_t hh, ll;
                    packhl(v0, v1, hh, ll);
                    *(uint32_t*)(OH + idx) = hh;
                    if (OL) *(uint32_t*)(OL + idx) = ll;
                } else {
                    *(float2*)(OF + (size_t)m * DMODEL + col) = make_float2(v0, v1);
                }
            }
        }
    }
}

__global__ __launch_bounds__(128) void k_mma_qkv(const float* __restrict__ bq,
                                                 const float* __restrict__ bk,
                                                 const float* __restrict__ bv) {
    int z = blockIdx.z;
    const __half* Ah = g_actH + (size_t)z * DMODEL * DMODEL;
    const __half* Al = g_actL + (size_t)z * DMODEL * DMODEL;
    const __half* Bh = g_WtH + (size_t)z * DMODEL * DMODEL;
    const float* bias = (z == 0) ? bq : (z == 1) ? bk : bv;
    __half* OH = (z == 0) ? g_QH : (z == 1) ? g_KH : g_VH;
    __half* OL = (z == 0) ? g_QL : (z == 1) ? g_KL : nullptr;   // V needs hi only
    float scale = (z == 0) ? 0.125f : 1.0f;
    mma_body<0>(Ah, Al, Bh, bias, OH, OL, nullptr, scale, z != 2);  // V: 1-term
}

__global__ __launch_bounds__(128) void k_mma_out(const float* __restrict__ bo,
                                                 float* __restrict__ out) {
    // out-proj: 1-term A (attn output hi only)
    mma_body<1>(g_attH, nullptr, g_WtH + (size_t)3 * DMODEL * DMODEL,
                bo, nullptr, nullptr, out, 1.0f, false);
}

// ---------------- tensor-core flash attention, 8 warps, fixed-max softmax ----------------
// S-stage K fragments: ONE ldsm_x4 loads kh[2]+kl[2] (lane groups 0-1 -> KH buffer,
// groups 2-3 -> KL buffer; identical row/col arithmetic, base chosen once per thread).
__global__ __launch_bounds__(256) void k_attn() {
    __shared__ __align__(1024) char smbuf[40960];
    uint32_t sQH = smem_u32(smbuf), sQL = sQH + 8192;
    uint32_t sKH = sQH + 16384, sKL = sQH + 24576;
    uint32_t sVH = sQH + 32768;
    int b = blockIdx.z, h = blockIdx.y, q0 = blockIdx.x * 64;
    int tid = threadIdx.x, lane = tid & 31, wid = tid >> 5;
    int wq = wid & 3, g = wid >> 2;
    size_t hb = (size_t)(b * NH + h) * SEQ * HDIM;
    const __half *QHp = g_QH + hb, *QLp = g_QL + hb;
    const __half *KHp = g_KH + hb, *KLp = g_KL + hb;
    const __half *VHp = g_VH + hb;
    const __half* Bg = g_bias + ((size_t)(b * NH + h) * SEQ + q0) * SEQ;
    uint32_t sKsel = (lane < 16) ? sKH : sKL;   // per-thread K buffer base (loop-invariant)

#pragma unroll
    for (int u = 0; u < 2; u++) {
        int idx = u * 256 + tid;
        int row = idx >> 3, c = idx & 7, cs = c ^ (row & 7);
        size_t go = (size_t)(q0 + row) * HDIM + c * 8;
        cp_async16(sQH + row * 128 + cs * 16, QHp + go);
        cp_async16(sQL + row * 128 + cs * 16, QLp + go);
    }
    CP_COMMIT();
    CP_WAIT(0);
    __syncthreads();

    uint32_t qh[4][4], ql[4][4];
#pragma unroll
    for (int kk = 0; kk < 4; kk++) {
        int row = wq * 16 + (lane & 15);
        int c = kk * 2 + (lane >> 4), cs = c ^ (row & 7);
        ldsm_x4(qh[kk], sQH + row * 128 + cs * 16);
        ldsm_x4(ql[kk], sQL + row * 128 + cs * 16);
    }

    float o[8][4];
#pragma unroll
    for (int j = 0; j < 8; j++)
#pragma unroll
        for (int r = 0; r < 4; r++) o[j][r] = 0.f;
    float lA = 0.f, lB = 0.f;
    int br0 = wq * 16 + (lane >> 2);
    int bc = 2 * (lane & 3);
    int goff = g * 32;

    for (int k0 = 0; k0 < SEQ; k0 += 64) {
        __syncthreads();
#pragma unroll
        for (int u = 0; u < 2; u++) {
            int idx = u * 256 + tid;
            int row = idx >> 3, c = idx & 7, cs = c ^ (row & 7);
            size_t go = (size_t)(k0 + row) * HDIM + c * 8;
            cp_async16(sKH + row * 128 + cs * 16, KHp + go);
            cp_async16(sKL + row * 128 + cs * 16, KLp + go);
            cp_async16(sVH + row * 128 + cs * 16, VHp + go);
        }
        CP_COMMIT();
        float2 bias0[4], bias1[4];
#pragma unroll
        for (int jt = 0; jt < 4; jt++) {
            __half2 t0 = *(const __half2*)(Bg + (size_t)br0 * SEQ + k0 + goff + jt * 8 + bc);
            __half2 t1 = *(const __half2*)(Bg + (size_t)(br0 + 8) * SEQ + k0 + goff + jt * 8 + bc);
            bias0[jt] = __half22float2(t0);
            bias1[jt] = __half22float2(t1);
        }
        CP_WAIT(0);
        __syncthreads();

        // S tiles: fused KH/KL ldsm_x4 (kb[0..1]=KH halves, kb[2..3]=KL halves)
        float s[4][4];
#pragma unroll
        for (int jt = 0; jt < 4; jt++) {
            s[jt][0] = s[jt][1] = s[jt][2] = s[jt][3] = 0.f;
#pragma unroll
            for (int kk = 0; kk < 4; kk++) {
                uint32_t kb[4];
                int row = goff + jt * 8 + (lane & 7);
                int c = kk * 2 + ((lane >> 3) & 1), cs = c ^ (row & 7);
                ldsm_x4(kb, sKsel + row * 128 + cs * 16);
                mma16816(s[jt], qh[kk], &kb[0]);
                mma16816(s[jt], ql[kk], &kb[0]);
                mma16816(s[jt], qh[kk], &kb[2]);
            }
        }

#pragma unroll
        for (int jt = 0; jt < 4; jt++) {
            s[jt][0] = __expf(s[jt][0] + bias0[jt].x);
            s[jt][1] = __expf(s[jt][1] + bias0[jt].y);
            s[jt][2] = __expf(s[jt][2] + bias1[jt].x);
            s[jt][3] = __expf(s[jt][3] + bias1[jt].y);
            lA += s[jt][0] + s[jt][1];
            lB += s[jt][2] + s[jt][3];
        }

        uint32_t ph[2][4], pl[2][4];
#pragma unroll
        for (int kk = 0; kk < 2; kk++) {
            packhl(s[2 * kk][0], s[2 * kk][1], ph[kk][0], pl[kk][0]);
            packhl(s[2 * kk][2], s[2 * kk][3], ph[kk][1], pl[kk][1]);
            packhl(s[2 * kk + 1][0], s[2 * kk + 1][1], ph[kk][2], pl[kk][2]);
            packhl(s[2 * kk + 1][2], s[2 * kk + 1][3], ph[kk][3], pl[kk][3]);
        }

#pragma unroll
        for (int kk = 0; kk < 2; kk++) {
#pragma unroll
            for (int j = 0; j < 8; j++) {
                uint32_t vh[2];
                int row = goff + kk * 16 + (lane & 15);
                int cs = j ^ (row & 7);
                ldsm_x2_trans(vh, sVH + row * 128 + cs * 16);
                mma16816(o[j], ph[kk], vh);
                mma16816(o[j], pl[kk], vh);
            }
        }
    }

    lA += __shfl_xor_sync(0xffffffffu, lA, 1);
    lA += __shfl_xor_sync(0xffffffffu, lA, 2);
    lB += __shfl_xor_sync(0xffffffffu, lB, 1);
    lB += __shfl_xor_sync(0xffffffffu, lB, 2);

    float* scr = (float*)(smbuf + 16384);
    float* sml = (float*)(smbuf + 32768);
    __syncthreads();
    if (g == 1) {
#pragma unroll
        for (int j = 0; j < 8; j++) {
            scr[br0 * 64 + j * 8 + bc] = o[j][0];
            scr[br0 * 64 + j * 8 + bc + 1] = o[j][1];
            scr[(br0 + 8) * 64 + j * 8 + bc] = o[j][2];
            scr[(br0 + 8) * 64 + j * 8 + bc + 1] = o[j][3];
        }
        if ((lane & 3) == 0) {
            sml[br0] = lA;
            sml[br0 + 8] = lB;
        }
    }
    __syncthreads();
    if (g == 0) {
        float r0 = 1.f / (lA + sml[br0]);
        float r1 = 1.f / (lB + sml[br0 + 8]);
        int rq0 = q0 + br0;
#pragma unroll
        for (int j = 0; j < 8; j++) {
            float v0 = (o[j][0] + scr[br0 * 64 + j * 8 + bc]) * r0;
            float v1 = (o[j][1] + scr[br0 * 64 + j * 8 + bc + 1]) * r0;
            float v2 = (o[j][2] + scr[(br0 + 8) * 64 + j * 8 + bc]) * r1;
            float v3 = (o[j][3] + scr[(br0 + 8) * 64 + j * 8 + bc + 1]) * r1;
            size_t i0 = ((size_t)(b * SEQ + rq0) * NH + h) * HDIM + j * 8 + bc;
            size_t i1 = ((size_t)(b * SEQ + rq0 + 8) * NH + h) * HDIM + j * 8 + bc;
            __half2 h0 = __floats2half2_rn(v0, v1);
            __half2 h1 = __floats2half2_rn(v2, v3);
            *(__half2*)(g_attH + i0) = h0;
            *(__half2*)(g_attH + i1) = h1;
        }
    }
}

// ---------------- launch: two-stream fork/join for graph-level overlap ----------------
extern "C" void kernel_launch(void* const* d_in, const int* in_sizes, int n_in,
                              void* d_out, int out_size) {
    (void)in_sizes; (void)n_in; (void)out_size;
    const float* query = (const float*)d_in[0];
    const float* key   = (const float*)d_in[1];
    const float* value = (const float*)d_in[2];
    const float* qx    = (const float*)d_in[3];
    const float* qy    = (const float*)d_in[4];
    const float* kx    = (const float*)d_in[5];
    const float* ky    = (const float*)d_in[6];
    const float* Wq    = (const float*)d_in[7];
    const float* bq    = (const float*)d_in[8];
    const float* Wk    = (const float*)d_in[9];
    const float* bk    = (const float*)d_in[10];
    const float* Wv    = (const float*)d_in[11];
    const float* bv    = (const float*)d_in[12];
    const float* Wo    = (const float*)d_in[13];
    const float* bo    = (const float*)d_in[14];
    const float* xt    = (const float*)d_in[15];
    const float* yt    = (const float*)d_in[16];
    const float* Wb    = (const float*)d_in[17];
    const float* bb    = (const float*)d_in[18];
    float* out = (float*)d_out;

    static cudaStream_t s1 = nullptr;
    static cudaEvent_t eFork = nullptr, eJoin = nullptr;
    if (!s1) {
        cudaStreamCreateWithFlags(&s1, cudaStreamNonBlocking);
        cudaEventCreateWithFlags(&eFork, cudaEventDisableTiming);
        cudaEventCreateWithFlags(&eJoin, cudaEventDisableTiming);
    }

    // fork: side stream runs the memory-bound bias chain
    cudaEventRecord(eFork, 0);
    cudaStreamWaitEvent(s1, eFork, 0);
    k_project<<<(2 * NEMB * NH + 255) / 256, 256, 0, s1>>>(xt, yt, Wb);
    k_bias<<<dim3(SEQ / 16, SEQ / 16, NB), 256, 0, s1>>>(qx, qy, kx, ky, bb);
    cudaEventRecord(eJoin, s1);

    // main stream: mma-bound projection chain (overlaps with bias chain)
    k_conv<<<7168, 256>>>(query, key, value, Wq, Wk, Wv, Wo);
    k_mma_qkv<<<dim3(DMODEL / 64, (NB * SEQ) / 64, 3), 128>>>(bq, bk, bv);

    // join: attention needs both chains
    cudaStreamWaitEvent(0, eJoin, 0);
    k_attn<<<dim3(SEQ / 64, NH, NB), 256>>>();
    k_mma_out<<<dim3(DMODEL / 64, DMODEL / 64), 128>>>(bo, out);
}

// round 16
// speedup vs baseline: 1.1276x; 1.0167x over previous
#include <cuda_runtime.h>
#include <cuda_fp16.h>
#include <cstdint>

#define NH     16
#define DMODEL 1024
#define HDIM   64
#define NEMB   40001
#define NB     2
#define SEQ    512

// ---------------- device scratch ----------------
__device__ float g_Tx[NEMB * NH];
__device__ float g_Ty[NEMB * NH];
__device__ __half g_bias[(size_t)NB * NH * SEQ * SEQ];   // fp16 bias (16.7MB)

// fp16 hi/lo split operands
__device__ __half g_actH[3 * DMODEL * DMODEL];   // q,k,v activations [m][k]
__device__ __half g_actL[3 * DMODEL * DMODEL];
__device__ __half g_WtH[4 * DMODEL * DMODEL];    // Wq,Wk,Wv,Wo transposed [n][k] (hi only)
// projected Q/K/V in [b][h][seq][d], fp16 hi/lo (Q pre-scaled by 0.125)
__device__ __half g_QH[NB * NH * SEQ * HDIM], g_QL[NB * NH * SEQ * HDIM];
__device__ __half g_KH[NB * NH * SEQ * HDIM], g_KL[NB * NH * SEQ * HDIM];
__device__ __half g_VH[NB * NH * SEQ * HDIM];
// attention output (hi only), [b*q][h*64+d] row-major 1024x1024
__device__ __half g_attH[DMODEL * DMODEL];

// ---------------- non-gated PTX helpers ----------------
__device__ __forceinline__ uint32_t smem_u32(const void* p) {
    uint32_t a;
    asm("{ .reg .u64 t; cvta.to.shared.u64 t, %1; cvt.u32.u64 %0, t; }" : "=r"(a) : "l"(p));
    return a;
}
__device__ __forceinline__ void cp_async16(uint32_t saddr, const void* gptr) {
    asm volatile("cp.async.cg.shared.global [%0], [%1], 16;" :: "r"(saddr), "l"(gptr) : "memory");
}
#define CP_COMMIT() asm volatile("cp.async.commit_group;" ::: "memory")
#define CP_WAIT(n)  asm volatile("cp.async.wait_group %0;" :: "n"(n) : "memory")

__device__ __forceinline__ void ldsm_x4(uint32_t* r, uint32_t addr) {
    asm volatile("ldmatrix.sync.aligned.m8n8.x4.shared.b16 {%0,%1,%2,%3}, [%4];"
                 : "=r"(r[0]), "=r"(r[1]), "=r"(r[2]), "=r"(r[3]) : "r"(addr));
}
__device__ __forceinline__ void ldsm_x2_trans(uint32_t* r, uint32_t addr) {
    asm volatile("ldmatrix.sync.aligned.m8n8.x2.trans.shared.b16 {%0,%1}, [%2];"
                 : "=r"(r[0]), "=r"(r[1]) : "r"(addr));
}
__device__ __forceinline__ void mma16816(float* d, const uint32_t* a, const uint32_t* b) {
    asm volatile("mma.sync.aligned.m16n8k16.row.col.f32.f16.f16.f32 "
                 "{%0,%1,%2,%3}, {%4,%5,%6,%7}, {%8,%9}, {%0,%1,%2,%3};"
                 : "+f"(d[0]), "+f"(d[1]), "+f"(d[2]), "+f"(d[3])
                 : "r"(a[0]), "r"(a[1]), "r"(a[2]), "r"(a[3]), "r"(b[0]), "r"(b[1]));
}
// pack two floats into fp16x2 hi part + fp16x2 residual part
__device__ __forceinline__ void packhl(float a, float b, uint32_t& hh, uint32_t& ll) {
    __half2 h2 = __floats2half2_rn(a, b);
    float2 f = __half22float2(h2);
    __half2 l2 = __floats2half2_rn(a - f.x, b - f.y);
    hh = *reinterpret_cast<uint32_t*>(&h2);
    ll = *reinterpret_cast<uint32_t*>(&l2);
}

// ---------------- kernel 1: project embedding tables through Wb ----------------
__global__ __launch_bounds__(256) void k_project(const float* __restrict__ xt,
                                                 const float* __restrict__ yt,
                                                 const float* __restrict__ Wb) {
    int id = blockIdx.x * 256 + threadIdx.x;
    if (id >= 2 * NEMB * NH) return;
    int which = (id >= NEMB * NH);
    int rid = which ? id - NEMB * NH : id;
    int r = rid >> 4, h = rid & 15;
    const float4* row = (const float4*)((which ? yt : xt) + (size_t)r * 256 + h * 16);
    const float4* wb = (const float4*)Wb;
    float s = 0.f;
#pragma unroll
    for (int q = 0; q < 4; q++) {
        float4 v = row[q], w = wb[q];
        s += v.x * w.x + v.y * w.y + v.z * w.z + v.w * w.w;
    }
    (which ? g_Ty : g_Tx)[rid] = s;
}

// ---------------- kernel 2: positional bias (fp16 output) ----------------
__global__ __launch_bounds__(256) void k_bias(const float* __restrict__ qx,
                                              const float* __restrict__ qy,
                                              const float* __restrict__ kx,
                                              const float* __restrict__ ky,
                                              const float* __restrict__ bbp) {
    __shared__ float sm[16 * 256];
    int b = blockIdx.z;
    int i0 = blockIdx.y * 16, j0 = blockIdx.x * 16;
    int t = threadIdx.x;
    int i = i0 + (t >> 4), j = j0 + (t & 15);
    float bb = bbp[0];
    float dx = qx[b * SEQ + j] - kx[b * SEQ + i];
    float dy = qy[b * SEQ + j] - ky[b * SEQ + i];
    dx = fminf(fmaxf(dx, -1000.f), 1000.f);
    dy = fminf(fmaxf(dy, -1000.f), 1000.f);
    int ix = (int)rintf((dx + 1000.f) * 20.f);
    int iy = (int)rintf((dy + 1000.f) * 20.f);
    const float4* px = (const float4*)(g_Tx + (size_t)ix * 16);
    const float4* py = (const float4*)(g_Ty + (size_t)iy * 16);
#pragma unroll
    for (int q = 0; q < 4; q++) {
        float4 a = px[q], c = py[q];
        float v0 = a.x + c.x + bb, v1 = a.y + c.y + bb;
        float v2 = a.z + c.z + bb, v3 = a.w + c.w + bb;
        sm[(q * 4 + 0) * 256 + t] = 1.f / (1.f + __expf(-v0));
        sm[(q * 4 + 1) * 256 + t] = 1.f / (1.f + __expf(-v1));
        sm[(q * 4 + 2) * 256 + t] = 1.f / (1.f + __expf(-v2));
        sm[(q * 4 + 3) * 256 + t] = 1.f / (1.f + __expf(-v3));
    }
    __syncthreads();
    int h = t >> 4, w = t & 15;
#pragma unroll
    for (int ii = 0; ii < 16; ii++) {
        g_bias[(((size_t)(b * NH + h)) * SEQ + (i0 + ii)) * SEQ + (j0 + w)] =
            __float2half(sm[h * 256 + ii * 16 + w]);
    }
}

// ---------------- fp16 hi/lo split helpers ----------------
__device__ __forceinline__ void split4h(float4 x, __half2* ph, __half2* pl) {
    __half2 h01 = __floats2half2_rn(x.x, x.y);
    __half2 h23 = __floats2half2_rn(x.z, x.w);
    float2 f01 = __half22float2(h01), f23 = __half22float2(h23);
    ph[0] = h01; ph[1] = h23;
    pl[0] = __floats2half2_rn(x.x - f01.x, x.y - f01.y);
    pl[1] = __floats2half2_rn(x.z - f23.x, x.w - f23.y);
}

// ---------------- merged conversion kernel: activations + weights ----------------
__global__ __launch_bounds__(256) void k_conv(const float* __restrict__ q,
                                              const float* __restrict__ k,
                                              const float* __restrict__ v,
                                              const float* __restrict__ Wq,
                                              const float* __restrict__ Wk,
                                              const float* __restrict__ Wv,
                                              const float* __restrict__ Wo) {
    __shared__ float t[32][33];
    int bidx = blockIdx.x, tid = threadIdx.x;
    if (bidx < 3072) {
        int z = bidx >> 10;
        const float* src = (z == 0) ? q : (z == 1) ? k : v;
        __half* H = g_actH + (size_t)z * DMODEL * DMODEL;
        __half* L = g_actL + (size_t)z * DMODEL * DMODEL;
        int i = (bidx & 1023) * 256 + tid;
        float4 x = ((const float4*)src)[i];
        split4h(x, (__half2*)(H + (size_t)i * 4), (__half2*)(L + (size_t)i * 4));
    } else {
        int w = bidx - 3072;
        int z = w >> 10, rem = w & 1023;
        const float* W = (z == 0) ? Wq : (z == 1) ? Wk : (z == 2) ? Wv : Wo;
        __half* H = g_WtH + (size_t)z * DMODEL * DMODEL;
        int nb = (rem & 31) * 32, kb = (rem >> 5) * 32;
        int tx = tid & 31, ty = tid >> 5;   // 32 x 8
#pragma unroll
        for (int i = 0; i < 4; i++)
            t[ty + i * 8][tx] = W[(size_t)(kb + ty + i * 8) * DMODEL + nb + tx];
        __syncthreads();
#pragma unroll
        for (int i = 0; i < 4; i++) {
            int n = nb + ty + i * 8, kk = kb + tx;
            H[(size_t)n * DMODEL + kk] = __float2half(t[tx][ty + i * 8]);
        }
    }
}

// ---------------- warp-mma GEMM: C = (Ah[+Al]) @ Bh^T + bias ----------------
// BM=BN=64, BK=32, 128 threads, 4 warps (2m x 2n), 3-stage pipeline, 1 sync/iter.
#define NKITER 32
#define STAGES 3

template <int MODE>
__device__ __forceinline__ void mma_body(const __half* __restrict__ Ah,
                                         const __half* __restrict__ Al,
                                         const __half* __restrict__ Bh,
                                         const float* __restrict__ bias,
                                         __half* __restrict__ OH,
                                         __half* __restrict__ OL,
                                         float* __restrict__ OF,
                                         float scale, bool useLo) {
    __shared__ __align__(1024) char smem[STAGES][12288];   // Ah 4KB | Al 4KB | B 4KB
    int tid = threadIdx.x, lane = tid & 31, wid = tid >> 5;
    int wm = wid & 1, wn = wid >> 1;                  // 2 x 2 warp grid
    int m0 = blockIdx.y * 64, n0 = blockIdx.x * 64;
    uint32_t sbase = smem_u32(smem);

    float acc[2][4][4];
#pragma unroll
    for (int i = 0; i < 2; i++)
#pragma unroll
        for (int j = 0; j < 4; j++)
#pragma unroll
            for (int r = 0; r < 4; r++) acc[i][j][r] = 0.f;

    auto issue_tile = [&](int ki, int s) {
        int kk = ki * 32;
        uint32_t sAh = sbase + s * 12288, sAl = sAh + 4096, sB = sAh + 8192;
#pragma unroll
        for (int j = 0; j < 2; j++) {
            int idx = tid + j * 128;                   // 256 chunks per tile
            int row = idx >> 2, c = idx & 3;
            int cs = c ^ ((row >> 1) & 3);
            size_t ga = (size_t)(m0 + row) * DMODEL + kk + c * 8;
            cp_async16(sAh + row * 64 + cs * 16, Ah + ga);
            if (useLo) cp_async16(sAl + row * 64 + cs * 16, Al + ga);
            cp_async16(sB + row * 64 + cs * 16, Bh + (size_t)(n0 + row) * DMODEL + kk + c * 8);
        }
        CP_COMMIT();
    };

    issue_tile(0, 0);
    issue_tile(1, 1);
    for (int ki = 0; ki < NKITER; ki++) {
        int s = ki % STAGES;
        if (ki + 1 < NKITER) { CP_WAIT(1); } else { CP_WAIT(0); }
        __syncthreads();
        if (ki + 2 < NKITER) issue_tile(ki + 2, (ki + 2) % STAGES);
        uint32_t sAh = sbase + s * 12288, sAl = sAh + 4096, sB = sAh + 8192;
#pragma unroll
        for (int kq = 0; kq < 2; kq++) {
            uint32_t ah[2][4], al[2][4];
#pragma unroll
            for (int im = 0; im < 2; im++) {
                int row = wm * 32 + im * 16 + (lane & 15);
                int c = kq * 2 + (lane >> 4);
                int cs = c ^ ((row >> 1) & 3);
                ldsm_x4(ah[im], sAh + row * 64 + cs * 16);
                if (useLo) ldsm_x4(al[im], sAl + row * 64 + cs * 16);
            }
#pragma unroll
            for (int jnp = 0; jnp < 2; jnp++) {
                uint32_t bf[4];                          // 2 n-tiles x 2 k8 halves
                int mat = lane >> 3;
                int jn2 = jnp * 2 + (mat >> 1);
                int cc = kq * 2 + (mat & 1);
                int row = wn * 32 + jn2 * 8 + (lane & 7);
                int cs = cc ^ ((row >> 1) & 3);
                ldsm_x4(bf, sB + row * 64 + cs * 16);
#pragma unroll
                for (int im = 0; im < 2; im++) {
                    mma16816(acc[im][jnp * 2 + 0], ah[im], &bf[0]);
                    mma16816(acc[im][jnp * 2 + 1], ah[im], &bf[2]);
                    if (useLo) {
                        mma16816(acc[im][jnp * 2 + 0], al[im], &bf[0]);
                        mma16816(acc[im][jnp * 2 + 1], al[im], &bf[2]);
                    }
                }
            }
        }
    }

    // epilogue
#pragma unroll
    for (int im = 0; im < 2; im++) {
#pragma unroll
        for (int jn = 0; jn < 4; jn++) {
            int col = n0 + wn * 32 + jn * 8 + 2 * (lane & 3);
            float b0 = bias[col], b1 = bias[col + 1];
#pragma unroll
            for (int half = 0; half < 2; half++) {
                int m = m0 + wm * 32 + im * 16 + (lane >> 2) + half * 8;
                float v0 = (acc[im][jn][half * 2 + 0] + b0) * scale;
                float v1 = (acc[im][jn][half * 2 + 1] + b1) * scale;
                if (MODE == 0) {
                    int bidx = m >> 9, nseq = m & 511;
                    int h = col >> 6, d = col & 63;
                    size_t idx = (((size_t)(bidx * NH + h)) * SEQ + nseq) * HDIM + d;
                    uint32_t hh, ll;
                    packhl(v0, v1, hh, ll);
                    *(uint32_t*)(OH + idx) = hh;
                    if (OL) *(uint32_t*)(OL + idx) = ll;
                } else {
                    *(float2*)(OF + (size_t)m * DMODEL + col) = make_float2(v0, v1);
                }
            }
        }
    }
}

__global__ __launch_bounds__(128) void k_mma_qkv(const float* __restrict__ bq,
                                                 const float* __restrict__ bk,
                                                 const float* __restrict__ bv) {
    int z = blockIdx.z;
    const __half* Ah = g_actH + (size_t)z * DMODEL * DMODEL;
    const __half* Al = g_actL + (size_t)z * DMODEL * DMODEL;
    const __half* Bh = g_WtH + (size_t)z * DMODEL * DMODEL;
    const float* bias = (z == 0) ? bq : (z == 1) ? bk : bv;
    __half* OH = (z == 0) ? g_QH : (z == 1) ? g_KH : g_VH;
    __half* OL = (z == 0) ? g_QL : (z == 1) ? g_KL : nullptr;   // V needs hi only
    float scale = (z == 0) ? 0.125f : 1.0f;
    mma_body<0>(Ah, Al, Bh, bias, OH, OL, nullptr, scale, z != 2);  // V: 1-term
}

__global__ __launch_bounds__(128) void k_mma_out(const float* __restrict__ bo,
                                                 float* __restrict__ out) {
    // out-proj: 1-term A (attn output hi only)
    mma_body<1>(g_attH, nullptr, g_WtH + (size_t)3 * DMODEL * DMODEL,
                bo, nullptr, nullptr, out, 1.0f, false);
}

// ---------------- tensor-core flash attention, 8 warps, fixed-max softmax ----------------
// S: fused KH/KL ldsm_x4 (3-term logits).  PV: 1-term (Ph·Vh) — P rounding errors are
// independent signed roundings, adding only ~3e-4 relative error to O.
__global__ __launch_bounds__(256) void k_attn() {
    __shared__ __align__(1024) char smbuf[40960];
    uint32_t sQH = smem_u32(smbuf), sQL = sQH + 8192;
    uint32_t sKH = sQH + 16384, sKL = sQH + 24576;
    uint32_t sVH = sQH + 32768;
    int b = blockIdx.z, h = blockIdx.y, q0 = blockIdx.x * 64;
    int tid = threadIdx.x, lane = tid & 31, wid = tid >> 5;
    int wq = wid & 3, g = wid >> 2;
    size_t hb = (size_t)(b * NH + h) * SEQ * HDIM;
    const __half *QHp = g_QH + hb, *QLp = g_QL + hb;
    const __half *KHp = g_KH + hb, *KLp = g_KL + hb;
    const __half *VHp = g_VH + hb;
    const __half* Bg = g_bias + ((size_t)(b * NH + h) * SEQ + q0) * SEQ;
    uint32_t sKsel = (lane < 16) ? sKH : sKL;   // per-thread K buffer base (loop-invariant)

#pragma unroll
    for (int u = 0; u < 2; u++) {
        int idx = u * 256 + tid;
        int row = idx >> 3, c = idx & 7, cs = c ^ (row & 7);
        size_t go = (size_t)(q0 + row) * HDIM + c * 8;
        cp_async16(sQH + row * 128 + cs * 16, QHp + go);
        cp_async16(sQL + row * 128 + cs * 16, QLp + go);
    }
    CP_COMMIT();
    CP_WAIT(0);
    __syncthreads();

    uint32_t qh[4][4], ql[4][4];
#pragma unroll
    for (int kk = 0; kk < 4; kk++) {
        int row = wq * 16 + (lane & 15);
        int c = kk * 2 + (lane >> 4), cs = c ^ (row & 7);
        ldsm_x4(qh[kk], sQH + row * 128 + cs * 16);
        ldsm_x4(ql[kk], sQL + row * 128 + cs * 16);
    }

    float o[8][4];
#pragma unroll
    for (int j = 0; j < 8; j++)
#pragma unroll
        for (int r = 0; r < 4; r++) o[j][r] = 0.f;
    float lA = 0.f, lB = 0.f;
    int br0 = wq * 16 + (lane >> 2);
    int bc = 2 * (lane & 3);
    int goff = g * 32;

    for (int k0 = 0; k0 < SEQ; k0 += 64) {
        __syncthreads();
#pragma unroll
        for (int u = 0; u < 2; u++) {
            int idx = u * 256 + tid;
            int row = idx >> 3, c = idx & 7, cs = c ^ (row & 7);
            size_t go = (size_t)(k0 + row) * HDIM + c * 8;
            cp_async16(sKH + row * 128 + cs * 16, KHp + go);
            cp_async16(sKL + row * 128 + cs * 16, KLp + go);
            cp_async16(sVH + row * 128 + cs * 16, VHp + go);
        }
        CP_COMMIT();
        float2 bias0[4], bias1[4];
#pragma unroll
        for (int jt = 0; jt < 4; jt++) {
            __half2 t0 = *(const __half2*)(Bg + (size_t)br0 * SEQ + k0 + goff + jt * 8 + bc);
            __half2 t1 = *(const __half2*)(Bg + (size_t)(br0 + 8) * SEQ + k0 + goff + jt * 8 + bc);
            bias0[jt] = __half22float2(t0);
            bias1[jt] = __half22float2(t1);
        }
        CP_WAIT(0);
        __syncthreads();

        // S tiles: fused KH/KL ldsm_x4 (kb[0..1]=KH halves, kb[2..3]=KL halves)
        float s[4][4];
#pragma unroll
        for (int jt = 0; jt < 4; jt++) {
            s[jt][0] = s[jt][1] = s[jt][2] = s[jt][3] = 0.f;
#pragma unroll
            for (int kk = 0; kk < 4; kk++) {
                uint32_t kb[4];
                int row = goff + jt * 8 + (lane & 7);
                int c = kk * 2 + ((lane >> 3) & 1), cs = c ^ (row & 7);
                ldsm_x4(kb, sKsel + row * 128 + cs * 16);
                mma16816(s[jt], qh[kk], &kb[0]);
                mma16816(s[jt], ql[kk], &kb[0]);
                mma16816(s[jt], qh[kk], &kb[2]);
            }
        }

#pragma unroll
        for (int jt = 0; jt < 4; jt++) {
            s[jt][0] = __expf(s[jt][0] + bias0[jt].x);
            s[jt][1] = __expf(s[jt][1] + bias0[jt].y);
            s[jt][2] = __expf(s[jt][2] + bias1[jt].x);
            s[jt][3] = __expf(s[jt][3] + bias1[jt].y);
            lA += s[jt][0] + s[jt][1];
            lB += s[jt][2] + s[jt][3];
        }

        // P fragments: hi only (1-term PV)
        uint32_t ph[2][4];
#pragma unroll
        for (int kk = 0; kk < 2; kk++) {
            __half2 p0 = __floats2half2_rn(s[2 * kk][0], s[2 * kk][1]);
            __half2 p1 = __floats2half2_rn(s[2 * kk][2], s[2 * kk][3]);
            __half2 p2 = __floats2half2_rn(s[2 * kk + 1][0], s[2 * kk + 1][1]);
            __half2 p3 = __floats2half2_rn(s[2 * kk + 1][2], s[2 * kk + 1][3]);
            ph[kk][0] = *reinterpret_cast<uint32_t*>(&p0);
            ph[kk][1] = *reinterpret_cast<uint32_t*>(&p1);
            ph[kk][2] = *reinterpret_cast<uint32_t*>(&p2);
            ph[kk][3] = *reinterpret_cast<uint32_t*>(&p3);
        }

#pragma unroll
        for (int kk = 0; kk < 2; kk++) {
#pragma unroll
            for (int j = 0; j < 8; j++) {
                uint32_t vh[2];
                int row = goff + kk * 16 + (lane & 15);
                int cs = j ^ (row & 7);
                ldsm_x2_trans(vh, sVH + row * 128 + cs * 16);
                mma16816(o[j], ph[kk], vh);
            }
        }
    }

    lA += __shfl_xor_sync(0xffffffffu, lA, 1);
    lA += __shfl_xor_sync(0xffffffffu, lA, 2);
    lB += __shfl_xor_sync(0xffffffffu, lB, 1);
    lB += __shfl_xor_sync(0xffffffffu, lB, 2);

    float* scr = (float*)(smbuf + 16384);
    float* sml = (float*)(smbuf + 32768);
    __syncthreads();
    if (g == 1) {
#pragma unroll
        for (int j = 0; j < 8; j++) {
            scr[br0 * 64 + j * 8 + bc] = o[j][0];
            scr[br0 * 64 + j * 8 + bc + 1] = o[j][1];
            scr[(br0 + 8) * 64 + j * 8 + bc] = o[j][2];
            scr[(br0 + 8) * 64 + j * 8 + bc + 1] = o[j][3];
        }
        if ((lane & 3) == 0) {
            sml[br0] = lA;
            sml[br0 + 8] = lB;
        }
    }
    __syncthreads();
    if (g == 0) {
        float r0 = 1.f / (lA + sml[br0]);
        float r1 = 1.f / (lB + sml[br0 + 8]);
        int rq0 = q0 + br0;
#pragma unroll
        for (int j = 0; j < 8; j++) {
            float v0 = (o[j][0] + scr[br0 * 64 + j * 8 + bc]) * r0;
            float v1 = (o[j][1] + scr[br0 * 64 + j * 8 + bc + 1]) * r0;
            float v2 = (o[j][2] + scr[(br0 + 8) * 64 + j * 8 + bc]) * r1;
            float v3 = (o[j][3] + scr[(br0 + 8) * 64 + j * 8 + bc + 1]) * r1;
            size_t i0 = ((size_t)(b * SEQ + rq0) * NH + h) * HDIM + j * 8 + bc;
            size_t i1 = ((size_t)(b * SEQ + rq0 + 8) * NH + h) * HDIM + j * 8 + bc;
            __half2 h0 = __floats2half2_rn(v0, v1);
            __half2 h1 = __floats2half2_rn(v2, v3);
            *(__half2*)(g_attH + i0) = h0;
            *(__half2*)(g_attH + i1) = h1;
        }
    }
}

// ---------------- launch: two-stream fork/join for graph-level overlap ----------------
extern "C" void kernel_launch(void* const* d_in, const int* in_sizes, int n_in,
                              void* d_out, int out_size) {
    (void)in_sizes; (void)n_in; (void)out_size;
    const float* query = (const float*)d_in[0];
    const float* key   = (const float*)d_in[1];
    const float* value = (const float*)d_in[2];
    const float* qx    = (const float*)d_in[3];
    const float* qy    = (const float*)d_in[4];
    const float* kx    = (const float*)d_in[5];
    const float* ky    = (const float*)d_in[6];
    const float* Wq    = (const float*)d_in[7];
    const float* bq    = (const float*)d_in[8];
    const float* Wk    = (const float*)d_in[9];
    const float* bk    = (const float*)d_in[10];
    const float* Wv    = (const float*)d_in[11];
    const float* bv    = (const float*)d_in[12];
    const float* Wo    = (const float*)d_in[13];
    const float* bo    = (const float*)d_in[14];
    const float* xt    = (const float*)d_in[15];
    const float* yt    = (const float*)d_in[16];
    const float* Wb    = (const float*)d_in[17];
    const float* bb    = (const float*)d_in[18];
    float* out = (float*)d_out;

    static cudaStream_t s1 = nullptr;
    static cudaEvent_t eFork = nullptr, eJoin = nullptr;
    if (!s1) {
        cudaStreamCreateWithFlags(&s1, cudaStreamNonBlocking);
        cudaEventCreateWithFlags(&eFork, cudaEventDisableTiming);
        cudaEventCreateWithFlags(&eJoin, cudaEventDisableTiming);
    }

    // fork: side stream runs the memory-bound bias chain
    cudaEventRecord(eFork, 0);
    cudaStreamWaitEvent(s1, eFork, 0);
    k_project<<<(2 * NEMB * NH + 255) / 256, 256, 0, s1>>>(xt, yt, Wb);
    k_bias<<<dim3(SEQ / 16, SEQ / 16, NB), 256, 0, s1>>>(qx, qy, kx, ky, bb);
    cudaEventRecord(eJoin, s1);

    // main stream: mma-bound projection chain (overlaps with bias chain)
    k_conv<<<7168, 256>>>(query, key, value, Wq, Wk, Wv, Wo);
    k_mma_qkv<<<dim3(DMODEL / 64, (NB * SEQ) / 64, 3), 128>>>(bq, bk, bv);

    // join: attention needs both chains
    cudaStreamWaitEvent(0, eJoin, 0);
    k_attn<<<dim3(SEQ / 64, NH, NB), 256>>>();
    k_mma_out<<<dim3(DMODEL / 64, DMODEL / 64), 128>>>(bo, out);
}